// round 14
// baseline (speedup 1.0000x reference)
#include <cuda_runtime.h>
#include <cuda_bf16.h>
#include <cfloat>
#include <math.h>
#include <stdint.h>
#include <string.h>

// ---------------- problem constants ----------------
static constexpr int kNH   = 16;
static constexpr int kS    = 512;
static constexpr int kH    = 2048;
static constexpr int kD    = 128;
static constexpr int kSC   = 8192;   // cache length
static constexpr int kTopK = 16;
static constexpr int kCand = 32;     // approx candidate pool per row
static constexpr int kQKVld = 3 * kH;          // 6144
static constexpr float kScale = 0.08838834764831845f;  // 1/sqrt(128)
static constexpr float kSimTh = 0.25f;
static constexpr float kNeg   = -1e30f;

// ---------------- scratch (__device__ globals; no allocation allowed) ----------------
__device__ __align__(16) float g_qkv[kS * kQKVld];                    // 12.6 MB
__device__ __align__(16) uint16_t g_simkey[(size_t)kNH * kS * kSC];   // 134 MB monotone keys
__device__ float g_topv[kNH * kS * kTopK];                            // exact vals
__device__ int   g_topi[kNH * kS * kTopK];                            // exact top-16 idx
__device__ int   g_cand[kNH * kS * kCand];                            // approx top-32 pool
__device__ __align__(16) float g_qn_f32[kNH * kS * kD];               // normalized q fp32
__device__ __align__(16) float g_kn_f32[(size_t)kNH * kSC * kD];      // normalized k fp32

// attention pipeline buffers
__device__ __align__(16) float g_scores[(size_t)kNH * kS * kS];       // 16.8 MB raw QK^T
__device__ __align__(16) float g_ctxe[kS * kH];                       // ext context
__device__ __align__(16) float g_ctxl[kS * kH];                       // local context

// bf16 operands
__device__ __align__(16) __nv_bfloat16 g_hid_h[kS * kH];
__device__ __align__(16) __nv_bfloat16 g_hid_l[kS * kH];
__device__ __align__(16) __nv_bfloat16 g_wqkv_h[kQKVld * kH];
__device__ __align__(16) __nv_bfloat16 g_wqkv_l[kQKVld * kH];
__device__ __align__(16) __nv_bfloat16 g_wout_h[kH * kH];
__device__ __align__(16) __nv_bfloat16 g_wout_l[kH * kH];
__device__ __align__(16) __nv_bfloat16 g_qn_h[kNH * kS * kD];
__device__ __align__(16) __nv_bfloat16 g_kn_h[kNH * kSC * kD];
__device__ __align__(16) __nv_bfloat16 g_ctx_h[kS * kH];
__device__ __align__(16) __nv_bfloat16 g_ctx_l[kS * kH];
__device__ __align__(16) __nv_bfloat16 g_lqk_h[kS * 4096];            // local Q|K bf16 hi
__device__ __align__(16) __nv_bfloat16 g_lqk_l[kS * 4096];            // local Q|K bf16 lo
__device__ __align__(16) __nv_bfloat16 g_vT_h[kNH * kD * kS];         // V^T bf16 hi
__device__ __align__(16) __nv_bfloat16 g_vT_l[kNH * kD * kS];         // V^T bf16 lo
__device__ __align__(16) __nv_bfloat16 g_pl_h[(size_t)kNH * kS * kS]; // P bf16 hi
__device__ __align__(16) __nv_bfloat16 g_pl_l[(size_t)kNH * kS * kS]; // P bf16 lo

// ================= warp-mma helpers (compute_103-safe: sm_80 mma.sync) ==========
__device__ __forceinline__ uint32_t smem_u32(const void* p) {
    uint32_t a;
    asm("{ .reg .u64 t; cvta.to.shared.u64 t, %1; cvt.u32.u64 %0, t; }" : "=r"(a) : "l"(p));
    return a;
}
__device__ __forceinline__ void ldsm_x4(uint32_t* r, uint32_t addr) {
    asm volatile("ldmatrix.sync.aligned.m8n8.x4.shared.b16 {%0,%1,%2,%3}, [%4];"
                 : "=r"(r[0]), "=r"(r[1]), "=r"(r[2]), "=r"(r[3]) : "r"(addr));
}
__device__ __forceinline__ void ldsm_x2(uint32_t* r, uint32_t addr) {
    asm volatile("ldmatrix.sync.aligned.m8n8.x2.shared.b16 {%0,%1}, [%2];"
                 : "=r"(r[0]), "=r"(r[1]) : "r"(addr));
}
__device__ __forceinline__ void mma_bf16(float* d, const uint32_t* a, const uint32_t* b) {
    asm volatile(
        "mma.sync.aligned.m16n8k16.row.col.f32.bf16.bf16.f32 "
        "{%0,%1,%2,%3}, {%4,%5,%6,%7}, {%8,%9}, {%0,%1,%2,%3};"
        : "+f"(d[0]), "+f"(d[1]), "+f"(d[2]), "+f"(d[3])
        : "r"(a[0]), "r"(a[1]), "r"(a[2]), "r"(a[3]), "r"(b[0]), "r"(b[1]));
}
// order-preserving uint16 key of a float (via bf16)
__device__ __forceinline__ uint16_t bf16_mono(float x) {
    __nv_bfloat16 b = __float2bfloat16(x);
    uint16_t u;
    memcpy(&u, &b, 2);
    return (u & 0x8000) ? (uint16_t)(~u) : (uint16_t)(u | 0x8000);
}

// ================= HMMA NT GEMM (NPROD products; NTILE=128/64; fp32/key16 out) ====
static constexpr int kRowB = 80;            // bytes per smem row (conflict-free ldmatrix)
static constexpr int kAMat = 128 * kRowB;   // 10240 (A tile always 128 rows)

template<int NPROD, bool KEY16, int NTILE>
__global__ void __launch_bounds__(256, (NTILE == 64 || NPROD == 1) ? 2 : 1)
mma_gemm(const __nv_bfloat16* __restrict__ Ah, const __nv_bfloat16* __restrict__ Al,
         const __nv_bfloat16* __restrict__ Bh, const __nv_bfloat16* __restrict__ Bl,
         void* __restrict__ Cv,
         int lda, int ldb, int ldc,
         long long aS, long long bS, long long cS, int K)
{
    constexpr int kBMat = NTILE * kRowB;
    constexpr int AH = 0;
    constexpr int AL = kAMat;                                   // used if NPROD==3
    constexpr int BH = (NPROD == 3) ? 2 * kAMat : kAMat;
    constexpr int BL = BH + kBMat;
    constexpr int STAGE = ((NPROD == 3) ? 2 * kAMat : kAMat) + ((NPROD == 3) ? 2 : 1) * kBMat;

    // warp layout: 8 warps tile 128 x NTILE
    constexpr int WY = (NTILE == 128) ? 2 : 4;   // warp rows
    constexpr int WX = 8 / WY;                   // warp cols
    constexpr int WM = 128 / WY;                 // rows per warp
    constexpr int WN = NTILE / WX;               // cols per warp
    constexpr int NI = WM / 16;                  // m16 frags
    constexpr int NJ = WN / 8;                   // n8 frags

    extern __shared__ char smem[];
    const uint32_t sb = smem_u32(smem);
    const int tid  = threadIdx.x;
    const int lane = tid & 31;
    const int warp = tid >> 5;
    const int wy = (NTILE == 128) ? (warp >> 2) : (warp >> 1);
    const int wx = (NTILE == 128) ? (warp & 3)  : (warp & 1);
    const int m0 = blockIdx.y * 128, n0 = blockIdx.x * NTILE, z = blockIdx.z;

    const __nv_bfloat16* pAh = Ah + (long long)z * aS;
    const __nv_bfloat16* pAl = (NPROD == 3) ? Al + (long long)z * aS : nullptr;
    const __nv_bfloat16* pBh = Bh + (long long)z * bS;
    const __nv_bfloat16* pBl = (NPROD == 3) ? Bl + (long long)z * bS : nullptr;

    float acc[NI][NJ][4];
#pragma unroll
    for (int i = 0; i < NI; i++)
#pragma unroll
        for (int j = 0; j < NJ; j++)
#pragma unroll
            for (int e = 0; e < 4; e++) acc[i][j][e] = 0.f;

    const int nCh = K >> 5;

    auto stageStore = [&](int c) {
        const int k0 = c << 5;
        char* stp = smem + (c & 1) * STAGE;
#pragma unroll
        for (int u = tid; u < 512; u += 256) {
            const int r = u >> 2, cc = u & 3;
            const long long ga = (long long)(m0 + r) * lda + k0 + cc * 8;
            const int so = r * kRowB + cc * 16;
            *(uint4*)(stp + AH + so) = *(const uint4*)(pAh + ga);
            if (NPROD == 3) *(uint4*)(stp + AL + so) = *(const uint4*)(pAl + ga);
        }
#pragma unroll
        for (int u = tid; u < NTILE * 4; u += 256) {
            const int r = u >> 2, cc = u & 3;
            const long long gb = (long long)(n0 + r) * ldb + k0 + cc * 8;
            const int so = r * kRowB + cc * 16;
            *(uint4*)(stp + BH + so) = *(const uint4*)(pBh + gb);
            if (NPROD == 3) *(uint4*)(stp + BL + so) = *(const uint4*)(pBl + gb);
        }
    };

    stageStore(0);
    __syncthreads();

    const int laneA_row = (lane & 15);
    const int laneA_cb  = (lane >> 4) * 16;
    const int laneB_row = (lane & 7);
    const int laneB_cb  = ((lane >> 3) & 1) * 16;

    for (int c = 0; c < nCh; c++) {
        if (c + 1 < nCh) stageStore(c + 1);

        const uint32_t stb = sb + (c & 1) * STAGE;
#pragma unroll
        for (int kf = 0; kf < 2; kf++) {
            const int kb = kf * 32;
            uint32_t a_h[NI][4], a_l[NI][4], b_h[NJ][2], b_l[NJ][2];
#pragma unroll
            for (int i = 0; i < NI; i++) {
                const uint32_t ra = stb + (uint32_t)((wy * WM + i * 16 + laneA_row) * kRowB + kb + laneA_cb);
                ldsm_x4(a_h[i], ra + AH);
                if (NPROD == 3) ldsm_x4(a_l[i], ra + AL);
            }
#pragma unroll
            for (int j = 0; j < NJ; j++) {
                const uint32_t rb = stb + (uint32_t)((wx * WN + j * 8 + laneB_row) * kRowB + kb + laneB_cb);
                ldsm_x2(b_h[j], rb + BH);
                if (NPROD == 3) ldsm_x2(b_l[j], rb + BL);
            }
#pragma unroll
            for (int i = 0; i < NI; i++)
#pragma unroll
                for (int j = 0; j < NJ; j++) {
                    mma_bf16(acc[i][j], a_h[i], b_h[j]);
                    if (NPROD == 3) {
                        mma_bf16(acc[i][j], a_h[i], b_l[j]);
                        mma_bf16(acc[i][j], a_l[i], b_h[j]);
                    }
                }
        }
        __syncthreads();
    }

    if (KEY16) {
        uint16_t* Cb = (uint16_t*)Cv + (long long)z * cS;
#pragma unroll
        for (int i = 0; i < NI; i++) {
            const int rr = m0 + wy * WM + i * 16 + (lane >> 2);
#pragma unroll
            for (int j = 0; j < NJ; j++) {
                const int cc = n0 + wx * WN + j * 8 + (lane & 3) * 2;
                const uint32_t k0 = (uint32_t)bf16_mono(acc[i][j][0]) | ((uint32_t)bf16_mono(acc[i][j][1]) << 16);
                const uint32_t k1 = (uint32_t)bf16_mono(acc[i][j][2]) | ((uint32_t)bf16_mono(acc[i][j][3]) << 16);
                *(uint32_t*)(Cb + (long long)rr * ldc + cc)       = k0;
                *(uint32_t*)(Cb + (long long)(rr + 8) * ldc + cc) = k1;
            }
        }
    } else {
        float* Cb = (float*)Cv + (long long)z * cS;
#pragma unroll
        for (int i = 0; i < NI; i++) {
            const int rr = m0 + wy * WM + i * 16 + (lane >> 2);
#pragma unroll
            for (int j = 0; j < NJ; j++) {
                const int cc = n0 + wx * WN + j * 8 + (lane & 3) * 2;
                float2 v0; v0.x = acc[i][j][0]; v0.y = acc[i][j][1];
                float2 v1; v1.x = acc[i][j][2]; v1.y = acc[i][j][3];
                *(float2*)(Cb + (long long)rr * ldc + cc)       = v0;
                *(float2*)(Cb + (long long)(rr + 8) * ldc + cc) = v1;
            }
        }
    }
}

static constexpr int kSmem3_128 = 2 * (4 * kAMat);                    // 81920
static constexpr int kSmem3_64  = 2 * (2 * kAMat + 2 * 64 * kRowB);   // 61440
static constexpr int kSmem1_128 = 2 * (2 * kAMat);                    // 40960

// ================= fp32 SGEMM 64x128 tile (exact path for Q projection) ==========
__global__ void __launch_bounds__(256, 2)
sgemm_nt(const float* __restrict__ A, int lda,
         const float* __restrict__ B, int ldb,
         float* __restrict__ C, int ldc, int K)
{
    __shared__ float As[16][64];
    __shared__ float Bs[16][128];

    const int tid = threadIdx.x;
    const int m0  = blockIdx.y * 64;
    const int n0  = blockIdx.x * 128;

    const int lr = tid >> 2;
    const int lc = (tid & 3) << 2;
    const int tx = tid & 15;
    const int ty = tid >> 4;

    float acc[4][8];
#pragma unroll
    for (int i = 0; i < 4; i++)
#pragma unroll
        for (int j = 0; j < 8; j++) acc[i][j] = 0.f;

    for (int k0 = 0; k0 < K; k0 += 16) {
        float4 a0 = *(const float4*)(A + (long long)(m0 + lr)      * lda + k0 + lc);
        float4 b0 = *(const float4*)(B + (long long)(n0 + lr)      * ldb + k0 + lc);
        float4 b1 = *(const float4*)(B + (long long)(n0 + lr + 64) * ldb + k0 + lc);
        __syncthreads();
        As[lc + 0][lr] = a0.x; As[lc + 1][lr] = a0.y; As[lc + 2][lr] = a0.z; As[lc + 3][lr] = a0.w;
        Bs[lc + 0][lr] = b0.x; Bs[lc + 1][lr] = b0.y; Bs[lc + 2][lr] = b0.z; Bs[lc + 3][lr] = b0.w;
        Bs[lc + 0][lr + 64] = b1.x; Bs[lc + 1][lr + 64] = b1.y; Bs[lc + 2][lr + 64] = b1.z; Bs[lc + 3][lr + 64] = b1.w;
        __syncthreads();
#pragma unroll
        for (int kk = 0; kk < 16; kk++) {
            float4 av = *(const float4*)&As[kk][ty * 4];
            float4 bv0 = *(const float4*)&Bs[kk][tx * 8];
            float4 bv1 = *(const float4*)&Bs[kk][tx * 8 + 4];
            float a[4] = {av.x, av.y, av.z, av.w};
            float b[8] = {bv0.x, bv0.y, bv0.z, bv0.w, bv1.x, bv1.y, bv1.z, bv1.w};
#pragma unroll
            for (int i = 0; i < 4; i++)
#pragma unroll
                for (int j = 0; j < 8; j++) acc[i][j] = fmaf(a[i], b[j], acc[i][j]);
        }
    }

#pragma unroll
    for (int i = 0; i < 4; i++) {
        float* crow = C + (long long)(m0 + ty * 4 + i) * ldc + n0 + tx * 8;
#pragma unroll
        for (int j = 0; j < 8; j++) crow[j] = acc[i][j];
    }
}

// ================= splits =================
__global__ void split_kernel(const float* __restrict__ src,
                             __nv_bfloat16* __restrict__ hi,
                             __nv_bfloat16* __restrict__ lo, int n4)
{
    const int i = blockIdx.x * blockDim.x + threadIdx.x;
    if (i >= n4) return;
    const float4 v = ((const float4*)src)[i];
    __nv_bfloat16 h0 = __float2bfloat16(v.x);
    __nv_bfloat16 h1 = __float2bfloat16(v.y);
    __nv_bfloat16 h2 = __float2bfloat16(v.z);
    __nv_bfloat16 h3 = __float2bfloat16(v.w);
    __nv_bfloat162 H0; H0.x = h0; H0.y = h1;
    __nv_bfloat162 H1; H1.x = h2; H1.y = h3;
    __nv_bfloat162 L0, L1;
    L0.x = __float2bfloat16(v.x - __bfloat162float(h0));
    L0.y = __float2bfloat16(v.y - __bfloat162float(h1));
    L1.x = __float2bfloat16(v.z - __bfloat162float(h2));
    L1.y = __float2bfloat16(v.w - __bfloat162float(h3));
    ((__nv_bfloat162*)hi)[2 * i]     = H0;
    ((__nv_bfloat162*)hi)[2 * i + 1] = H1;
    ((__nv_bfloat162*)lo)[2 * i]     = L0;
    ((__nv_bfloat162*)lo)[2 * i + 1] = L1;
}

// sum of two fp32 buffers -> bf16 hi/lo split
__global__ void sumsplit_kernel(const float* __restrict__ a, const float* __restrict__ b,
                                __nv_bfloat16* __restrict__ hi,
                                __nv_bfloat16* __restrict__ lo, int n4)
{
    const int i = blockIdx.x * blockDim.x + threadIdx.x;
    if (i >= n4) return;
    const float4 va = ((const float4*)a)[i];
    const float4 vb = ((const float4*)b)[i];
    float4 v;
    v.x = va.x + vb.x; v.y = va.y + vb.y; v.z = va.z + vb.z; v.w = va.w + vb.w;
    __nv_bfloat16 h0 = __float2bfloat16(v.x);
    __nv_bfloat16 h1 = __float2bfloat16(v.y);
    __nv_bfloat16 h2 = __float2bfloat16(v.z);
    __nv_bfloat16 h3 = __float2bfloat16(v.w);
    __nv_bfloat162 H0; H0.x = h0; H0.y = h1;
    __nv_bfloat162 H1; H1.x = h2; H1.y = h3;
    __nv_bfloat162 L0, L1;
    L0.x = __float2bfloat16(v.x - __bfloat162float(h0));
    L0.y = __float2bfloat16(v.y - __bfloat162float(h1));
    L1.x = __float2bfloat16(v.z - __bfloat162float(h2));
    L1.y = __float2bfloat16(v.w - __bfloat162float(h3));
    ((__nv_bfloat162*)hi)[2 * i]     = H0;
    ((__nv_bfloat162*)hi)[2 * i + 1] = H1;
    ((__nv_bfloat162*)lo)[2 * i]     = L0;
    ((__nv_bfloat162*)lo)[2 * i + 1] = L1;
}

// strided split of g_qkv columns [0,4096) (local Q|K) -> g_lqk hi/lo [512 x 4096]
__global__ void qksplit_kernel()
{
    const int i = blockIdx.x * blockDim.x + threadIdx.x;   // over 512*1024 float4
    if (i >= kS * 1024) return;
    const int row = i >> 10;
    const int c4  = (i & 1023) << 2;
    const float4 v = *(const float4*)&g_qkv[(long long)row * kQKVld + c4];
    __nv_bfloat16 h0 = __float2bfloat16(v.x);
    __nv_bfloat16 h1 = __float2bfloat16(v.y);
    __nv_bfloat16 h2 = __float2bfloat16(v.z);
    __nv_bfloat16 h3 = __float2bfloat16(v.w);
    __nv_bfloat162 H0; H0.x = h0; H0.y = h1;
    __nv_bfloat162 H1; H1.x = h2; H1.y = h3;
    __nv_bfloat162 L0, L1;
    L0.x = __float2bfloat16(v.x - __bfloat162float(h0));
    L0.y = __float2bfloat16(v.y - __bfloat162float(h1));
    L1.x = __float2bfloat16(v.z - __bfloat162float(h2));
    L1.y = __float2bfloat16(v.w - __bfloat162float(h3));
    ((__nv_bfloat162*)g_lqk_h)[2 * i]     = H0;
    ((__nv_bfloat162*)g_lqk_h)[2 * i + 1] = H1;
    ((__nv_bfloat162*)g_lqk_l)[2 * i]     = L0;
    ((__nv_bfloat162*)g_lqk_l)[2 * i + 1] = L1;
}

// V local transpose + split: g_qkv V part [k][h*128+d] -> g_vT [h][d][k] bf16 hi/lo
__global__ void vtrans_kernel()
{
    __shared__ float t[32][33];
    const int h  = blockIdx.z;
    const int dt = blockIdx.y;
    const int kt = blockIdx.x;
    const int tx = threadIdx.x & 31;
    const int ty = threadIdx.x >> 5;   // 0..7
#pragma unroll
    for (int i = 0; i < 4; i++) {
        const int k = kt * 32 + ty + i * 8;
        t[ty + i * 8][tx] = g_qkv[(long long)k * kQKVld + 2 * kH + h * kD + dt * 32 + tx];
    }
    __syncthreads();
#pragma unroll
    for (int i = 0; i < 4; i++) {
        const int d = dt * 32 + ty + i * 8;
        const float val = t[tx][ty + i * 8];
        const long long o = ((long long)h * kD + d) * kS + kt * 32 + tx;
        const __nv_bfloat16 hi = __float2bfloat16(val);
        g_vT_h[o] = hi;
        g_vT_l[o] = __float2bfloat16(val - __bfloat162float(hi));
    }
}

__global__ void qsplit_kernel()
{
    const int gw   = (blockIdx.x * blockDim.x + threadIdx.x) >> 5;
    const int lane = threadIdx.x & 31;
    if (gw >= kNH * kS) return;
    const int h = gw >> 9;
    const int q = gw & 511;
    float4 v = *(const float4*)(g_qkv + (long long)q * kQKVld + h * kD + lane * 4);
    float s = v.x * v.x + v.y * v.y + v.z * v.z + v.w * v.w;
#pragma unroll
    for (int o = 16; o > 0; o >>= 1) s += __shfl_xor_sync(0xffffffffu, s, o);
    const float inv = rsqrtf(s);
    v.x *= inv; v.y *= inv; v.z *= inv; v.w *= inv;
    const long long base = (long long)gw * kD + lane * 4;
    *(float4*)(g_qn_f32 + base) = v;
    __nv_bfloat162 H0, H1;
    H0.x = __float2bfloat16(v.x); H0.y = __float2bfloat16(v.y);
    H1.x = __float2bfloat16(v.z); H1.y = __float2bfloat16(v.w);
    *(__nv_bfloat162*)(g_qn_h + base)     = H0;
    *(__nv_bfloat162*)(g_qn_h + base + 2) = H1;
}

__global__ void ksplit_kernel(const float* __restrict__ kc)
{
    const int gw   = (blockIdx.x * blockDim.x + threadIdx.x) >> 5;
    const int lane = threadIdx.x & 31;
    if (gw >= kNH * kSC) return;
    float4 v = *(const float4*)(kc + (long long)gw * kD + lane * 4);
    float s = v.x * v.x + v.y * v.y + v.z * v.z + v.w * v.w;
#pragma unroll
    for (int o = 16; o > 0; o >>= 1) s += __shfl_xor_sync(0xffffffffu, s, o);
    const float inv = rsqrtf(s);
    v.x *= inv; v.y *= inv; v.z *= inv; v.w *= inv;
    const long long base = (long long)gw * kD + lane * 4;
    *(float4*)(g_kn_f32 + base) = v;
    __nv_bfloat162 H0, H1;
    H0.x = __float2bfloat16(v.x); H0.y = __float2bfloat16(v.y);
    H1.x = __float2bfloat16(v.z); H1.y = __float2bfloat16(v.w);
    *(__nv_bfloat162*)(g_kn_h + base)     = H0;
    *(__nv_bfloat162*)(g_kn_h + base + 2) = H1;
}

// ---------------- per-(h,q) approx top-32 over 8192 packed keys ----------------
// packed = key16 << 13 | (8191 - idx). Phase 1: per-warp top-32 (warp-sync only).
// Phase 2: warp 0 merges 8x32 -> exact top-32 (same set/order as block tournament).
__global__ void __launch_bounds__(256)
topk_kernel()
{
    const long long row = blockIdx.x;  // h*512 + q
    const uint16_t* sim = g_simkey + row * kSC;
    const int tid = threadIdx.x;
    const int lane = tid & 31;
    const int w = tid >> 5;

    uint32_t v[32];
#pragma unroll
    for (int c = 0; c < 4; c++) {
        const int base = c * 2048 + tid * 8;
        uint4 raw = *(const uint4*)(sim + base);
        const uint32_t words[4] = {raw.x, raw.y, raw.z, raw.w};
#pragma unroll
        for (int j = 0; j < 4; j++) {
            const uint32_t lo = words[j] & 0xFFFFu;
            const uint32_t hi = words[j] >> 16;
            v[c * 8 + 2 * j]     = (lo << 13) | (uint32_t)(8191 - (base + 2 * j));
            v[c * 8 + 2 * j + 1] = (hi << 13) | (uint32_t)(8191 - (base + 2 * j + 1));
        }
    }

    uint32_t locmax = 0;
#pragma unroll
    for (int i = 0; i < 32; i++) locmax = max(locmax, v[i]);

    __shared__ uint32_t cands[8][32];

    // phase 1: per-warp top-32, no block barriers
    for (int r = 0; r < kCand; r++) {
        const uint32_t wm = __reduce_max_sync(0xffffffffu, locmax);
        if (lane == (r & 31)) cands[w][r] = wm;
        if (locmax == wm) {
            uint32_t nm = 0;
#pragma unroll
            for (int i = 0; i < 32; i++) {
                if (v[i] == wm) v[i] = 0;
                nm = max(nm, v[i]);
            }
            locmax = nm;
        }
    }
    __syncthreads();

    // phase 2: warp 0 merges 256 candidates -> top-32 (descending)
    if (w == 0) {
        uint32_t c[8];
#pragma unroll
        for (int j = 0; j < 8; j++) c[j] = cands[j][lane];
        uint32_t lm = 0;
#pragma unroll
        for (int j = 0; j < 8; j++) lm = max(lm, c[j]);
        for (int r = 0; r < kCand; r++) {
            const uint32_t wm = __reduce_max_sync(0xffffffffu, lm);
            if (lane == 0) g_cand[row * kCand + r] = 8191 - (int)(wm & 8191u);
            if (lm == wm) {
                uint32_t nm = 0;
#pragma unroll
                for (int j = 0; j < 8; j++) {
                    if (c[j] == wm) c[j] = 0;
                    nm = max(nm, c[j]);
                }
                lm = nm;
            }
        }
    }
}

// ---------------- exact rescore of 32 candidates -> exact top-16 ----------------
__global__ void __launch_bounds__(256)
rescore_kernel()
{
    const int gw   = (blockIdx.x * blockDim.x + threadIdx.x) >> 5;
    const int lane = threadIdx.x & 31;
    if (gw >= kNH * kS) return;
    const int h = gw >> 9;

    const float4 qv = *(const float4*)(g_qn_f32 + (long long)gw * kD + lane * 4);
    int   myidx = g_cand[gw * kCand + lane];
    float myval = -FLT_MAX;

    for (int c = 0; c < kCand; c++) {
        const int idx = __shfl_sync(0xffffffffu, myidx, c);
        const float4 kv = *(const float4*)(g_kn_f32 + ((long long)h * kSC + idx) * kD + lane * 4);
        float p = qv.x * kv.x + qv.y * kv.y + qv.z * kv.z + qv.w * kv.w;
#pragma unroll
        for (int o = 16; o > 0; o >>= 1) p += __shfl_xor_sync(0xffffffffu, p, o);
        if (lane == c) myval = p;
    }

    for (int r = 0; r < kTopK; r++) {
        float v = myval; int ix = myidx;
#pragma unroll
        for (int o = 16; o > 0; o >>= 1) {
            float ov = __shfl_xor_sync(0xffffffffu, v, o);
            int   oi = __shfl_xor_sync(0xffffffffu, ix, o);
            if (ov > v || (ov == v && oi < ix)) { v = ov; ix = oi; }
        }
        if (lane == 0) {
            g_topv[gw * kTopK + r] = v;
            g_topi[gw * kTopK + r] = ix;
        }
        if (myidx == ix) myval = -FLT_MAX;
    }
}

// ---------------- softmax + ext context per (h,q) ----------------
__global__ void __launch_bounds__(256)
softmax_kernel(const float* __restrict__ kc, const float* __restrict__ vc,
               const float* __restrict__ bias)
{
    const int q = blockIdx.x;
    const int h = blockIdx.y;
    const int tid = threadIdx.x;
    const int lane = tid & 31;
    const int w = tid >> 5;

    __shared__ float qs[128];
    __shared__ float ssc[16 + kS];
    __shared__ int   sidx[16];
    __shared__ float redw[8];
    __shared__ float bmax, bsuminv;

    const long long rowhq = (long long)h * kS + q;

    if (tid < 128) qs[tid] = g_qkv[(long long)q * kQKVld + h * kD + tid];
    if (tid < 16)  sidx[tid] = g_topi[rowhq * 16 + tid];
    __syncthreads();

    const float4 qv = *(const float4*)(qs + lane * 4);

    for (int j = w; j < 16; j += 8) {
        float s;
        if (g_topv[rowhq * 16 + j] > kSimTh) {
            const float* kp = kc + ((long long)h * kSC + sidx[j]) * kD;
            float4 kv = *(const float4*)(kp + lane * 4);
            float p = qv.x * kv.x + qv.y * kv.y + qv.z * kv.z + qv.w * kv.w;
#pragma unroll
            for (int o = 16; o > 0; o >>= 1) p += __shfl_down_sync(0xffffffffu, p, o);
            s = p * kScale;
        } else {
            s = kNeg;
        }
        if (lane == 0) ssc[j] = s;
    }

    const float* srow  = g_scores + rowhq * kS;
    const float* brow  = bias + rowhq * kS;
    for (int j = tid; j < kS; j += 256) {
        ssc[16 + j] = (j <= q) ? srow[j] * kScale + brow[j] : kNeg;
    }
    __syncthreads();

    float m = -FLT_MAX;
    for (int j = tid; j < 16 + kS; j += 256) m = fmaxf(m, ssc[j]);
#pragma unroll
    for (int o = 16; o > 0; o >>= 1) m = fmaxf(m, __shfl_down_sync(0xffffffffu, m, o));
    if (lane == 0) redw[w] = m;
    __syncthreads();
    if (tid == 0) {
        float mm = redw[0];
#pragma unroll
        for (int k = 1; k < 8; k++) mm = fmaxf(mm, redw[k]);
        bmax = mm;
    }
    __syncthreads();
    const float msc = bmax;
    float ss = 0.f;
    for (int j = tid; j < 16 + kS; j += 256) {
        float e = __expf(ssc[j] - msc);
        ssc[j] = e;
        ss += e;
    }
#pragma unroll
    for (int o = 16; o > 0; o >>= 1) ss += __shfl_down_sync(0xffffffffu, ss, o);
    if (lane == 0) redw[w] = ss;
    __syncthreads();
    if (tid == 0) {
        float t = 0.f;
#pragma unroll
        for (int k = 0; k < 8; k++) t += redw[k];
        bsuminv = 1.f / t;
    }
    __syncthreads();
    const float inv = bsuminv;

    for (int j = tid; j < kS; j += 256) {
        const float p = ssc[16 + j] * inv;
        const __nv_bfloat16 hi = __float2bfloat16(p);
        g_pl_h[rowhq * kS + j] = hi;
        g_pl_l[rowhq * kS + j] = __float2bfloat16(p - __bfloat162float(hi));
    }

    if (tid < 128) {
        float acc = 0.f;
        for (int j = 0; j < 16; j++) {
            const float p = ssc[j] * inv;
            if (p > 0.f) acc += p * vc[((long long)h * kSC + sidx[j]) * kD + tid];
        }
        g_ctxe[(long long)q * kH + h * kD + tid] = acc;
    }
}

// ---------------- launcher ----------------
extern "C" void kernel_launch(void* const* d_in, const int* in_sizes, int n_in,
                              void* d_out, int out_size)
{
    const float* hidden = (const float*)d_in[0];
    const float* Wqkv   = (const float*)d_in[1];
    const float* Wout   = (const float*)d_in[2];
    const float* kc     = (const float*)d_in[3];
    const float* vc     = (const float*)d_in[4];
    const float* bias   = (const float*)d_in[5];
    float* out = (float*)d_out;

    float *p_qkv, *p_scores, *p_ctxe, *p_ctxl;
    uint16_t* p_simkey;
    cudaGetSymbolAddress((void**)&p_qkv,    g_qkv);
    cudaGetSymbolAddress((void**)&p_simkey, g_simkey);
    cudaGetSymbolAddress((void**)&p_scores, g_scores);
    cudaGetSymbolAddress((void**)&p_ctxe,   g_ctxe);
    cudaGetSymbolAddress((void**)&p_ctxl,   g_ctxl);
    __nv_bfloat16 *p_hid_h, *p_hid_l, *p_wqkv_h, *p_wqkv_l, *p_wout_h, *p_wout_l;
    __nv_bfloat16 *p_qn_h, *p_kn_h, *p_ctx_h, *p_ctx_l;
    __nv_bfloat16 *p_lqk_h, *p_lqk_l, *p_vT_h, *p_vT_l, *p_pl_h, *p_pl_l;
    cudaGetSymbolAddress((void**)&p_hid_h,  g_hid_h);
    cudaGetSymbolAddress((void**)&p_hid_l,  g_hid_l);
    cudaGetSymbolAddress((void**)&p_wqkv_h, g_wqkv_h);
    cudaGetSymbolAddress((void**)&p_wqkv_l, g_wqkv_l);
    cudaGetSymbolAddress((void**)&p_wout_h, g_wout_h);
    cudaGetSymbolAddress((void**)&p_wout_l, g_wout_l);
    cudaGetSymbolAddress((void**)&p_qn_h,   g_qn_h);
    cudaGetSymbolAddress((void**)&p_kn_h,   g_kn_h);
    cudaGetSymbolAddress((void**)&p_ctx_h,  g_ctx_h);
    cudaGetSymbolAddress((void**)&p_ctx_l,  g_ctx_l);
    cudaGetSymbolAddress((void**)&p_lqk_h,  g_lqk_h);
    cudaGetSymbolAddress((void**)&p_lqk_l,  g_lqk_l);
    cudaGetSymbolAddress((void**)&p_vT_h,   g_vT_h);
    cudaGetSymbolAddress((void**)&p_vT_l,   g_vT_l);
    cudaGetSymbolAddress((void**)&p_pl_h,   g_pl_h);
    cudaGetSymbolAddress((void**)&p_pl_l,   g_pl_l);

    cudaFuncSetAttribute((const void*)mma_gemm<3, false, 128>, cudaFuncAttributeMaxDynamicSharedMemorySize, kSmem3_128);
    cudaFuncSetAttribute((const void*)mma_gemm<3, false, 64>,  cudaFuncAttributeMaxDynamicSharedMemorySize, kSmem3_64);
    cudaFuncSetAttribute((const void*)mma_gemm<1, true, 128>,  cudaFuncAttributeMaxDynamicSharedMemorySize, kSmem1_128);

    // ---- selection chain first (sim mma = launch #3 for ncu visibility) ----
    // 0. normalized k cache (fp32 + bf16)
    ksplit_kernel<<<(kNH * kSC * 32) / 256, 256>>>(kc);
    // 1. Q projection EXACT fp32 (64x128 tiles, 128 CTAs)
    sgemm_nt<<<dim3(kH / 128, kS / 64), 256>>>(hidden, kH, Wqkv, kH, p_qkv, kQKVld, kH);
    // 2. normalized q (fp32 + bf16)
    qsplit_kernel<<<(kNH * kS * 32) / 256, 256>>>();
    // 3. approx cosine-sim GEMM -> 16-bit monotone keys (occ 2)
    mma_gemm<1, true, 128><<<dim3(kSC / 128, kS / 128, kNH), 256, kSmem1_128>>>(
        p_qn_h, nullptr, p_kn_h, nullptr, p_simkey,
        kD, kD, kSC,
        (long long)kS * kD, (long long)kSC * kD, (long long)kS * kSC, kD);
    // 4. approx top-32 pool (warp tournament) + 5. exact rescore
    topk_kernel<<<kNH * kS, 256>>>();
    rescore_kernel<<<(kNH * kS * 32 + 255) / 256, 256>>>();

    // ---- projection / attention chain ----
    split_kernel<<<(4096 * kH / 4 + 255) / 256, 256>>>(Wqkv + (size_t)2048 * kH, p_wqkv_h, p_wqkv_l, 4096 * kH / 4);
    split_kernel<<<(kS * kH / 4 + 255) / 256, 256>>>(hidden, p_hid_h, p_hid_l, kS * kH / 4);
    mma_gemm<3, false, 64><<<dim3(4096 / 64, kS / 128, 1), 256, kSmem3_64>>>(
        p_hid_h, p_hid_l, p_wqkv_h, p_wqkv_l,
        p_qkv + 2048, kH, kH, kQKVld, 0, 0, 0, kH);

    qksplit_kernel<<<(kS * 1024 + 255) / 256, 256>>>();
    mma_gemm<3, false, 128><<<dim3(kS / 128, kS / 128, kNH), 256, kSmem3_128>>>(
        p_lqk_h, p_lqk_l, p_lqk_h + 2048, p_lqk_l + 2048,
        p_scores, 4096, 4096, kS,
        128, 128, (long long)kS * kS, kD);

    vtrans_kernel<<<dim3(kS / 32, kD / 32, kNH), 256>>>();

    softmax_kernel<<<dim3(kS, kNH), 256>>>(kc, vc, bias);

    mma_gemm<3, false, 64><<<dim3(kD / 64, kS / 128, kNH), 256, kSmem3_64>>>(
        p_pl_h, p_pl_l, p_vT_h, p_vT_l,
        p_ctxl, kS, kS, kH,
        (long long)kS * kS, (long long)kD * kS, 128, kS);

    split_kernel<<<(kH * kH / 4 + 255) / 256, 256>>>(Wout, p_wout_h, p_wout_l, kH * kH / 4);
    sumsplit_kernel<<<(kS * kH / 4 + 255) / 256, 256>>>(p_ctxl, p_ctxe, p_ctx_h, p_ctx_l, kS * kH / 4);
    mma_gemm<3, false, 64><<<dim3(kH / 64, kS / 128, 1), 256, kSmem3_64>>>(
        p_ctx_h, p_ctx_l, p_wout_h, p_wout_l, out,
        kH, kH, kH, 0, 0, 0, kH);
}

// round 15
// speedup vs baseline: 1.1711x; 1.1711x over previous
#include <cuda_runtime.h>
#include <cuda_bf16.h>
#include <cfloat>
#include <math.h>
#include <stdint.h>
#include <string.h>

// ---------------- problem constants ----------------
static constexpr int kNH   = 16;
static constexpr int kS    = 512;
static constexpr int kH    = 2048;
static constexpr int kD    = 128;
static constexpr int kSC   = 8192;   // cache length
static constexpr int kTopK = 16;
static constexpr int kCand = 32;     // approx candidate pool per row
static constexpr int kQKVld = 3 * kH;          // 6144
static constexpr float kScale = 0.08838834764831845f;  // 1/sqrt(128)
static constexpr float kSimTh = 0.25f;
static constexpr float kNeg   = -1e30f;

// ---------------- scratch (__device__ globals; no allocation allowed) ----------------
__device__ __align__(16) float g_qkv[kS * kQKVld];                    // 12.6 MB
__device__ __align__(16) uint16_t g_simkey[(size_t)kNH * kS * kSC];   // 134 MB monotone keys
__device__ float g_topv[kNH * kS * kTopK];                            // exact vals
__device__ int   g_topi[kNH * kS * kTopK];                            // exact top-16 idx
__device__ int   g_cand[kNH * kS * kCand];                            // approx top-32 pool
__device__ __align__(16) float g_qn_f32[kNH * kS * kD];               // normalized q fp32
__device__ __align__(16) float g_kn_f32[(size_t)kNH * kSC * kD];      // normalized k fp32

// attention pipeline buffers
__device__ __align__(16) float g_scores[(size_t)kNH * kS * kS];       // 16.8 MB raw QK^T
__device__ __align__(16) float g_ctxe[kS * kH];                       // ext context
__device__ __align__(16) float g_ctxl[kS * kH];                       // local context

// bf16 operands
__device__ __align__(16) __nv_bfloat16 g_hid_h[kS * kH];
__device__ __align__(16) __nv_bfloat16 g_hid_l[kS * kH];
__device__ __align__(16) __nv_bfloat16 g_wqkv_h[kQKVld * kH];
__device__ __align__(16) __nv_bfloat16 g_wqkv_l[kQKVld * kH];
__device__ __align__(16) __nv_bfloat16 g_wout_h[kH * kH];
__device__ __align__(16) __nv_bfloat16 g_wout_l[kH * kH];
__device__ __align__(16) __nv_bfloat16 g_qn_h[kNH * kS * kD];
__device__ __align__(16) __nv_bfloat16 g_kn_h[kNH * kSC * kD];
__device__ __align__(16) __nv_bfloat16 g_ctx_h[kS * kH];
__device__ __align__(16) __nv_bfloat16 g_ctx_l[kS * kH];
__device__ __align__(16) __nv_bfloat16 g_lqk_h[kS * 4096];            // local Q|K bf16 hi
__device__ __align__(16) __nv_bfloat16 g_lqk_l[kS * 4096];            // local Q|K bf16 lo
__device__ __align__(16) __nv_bfloat16 g_vT_h[kNH * kD * kS];         // V^T bf16 hi
__device__ __align__(16) __nv_bfloat16 g_vT_l[kNH * kD * kS];         // V^T bf16 lo
__device__ __align__(16) __nv_bfloat16 g_pl_h[(size_t)kNH * kS * kS]; // P bf16 hi
__device__ __align__(16) __nv_bfloat16 g_pl_l[(size_t)kNH * kS * kS]; // P bf16 lo

// ================= warp-mma helpers (compute_103-safe: sm_80 mma.sync) ==========
__device__ __forceinline__ uint32_t smem_u32(const void* p) {
    uint32_t a;
    asm("{ .reg .u64 t; cvta.to.shared.u64 t, %1; cvt.u32.u64 %0, t; }" : "=r"(a) : "l"(p));
    return a;
}
__device__ __forceinline__ void ldsm_x4(uint32_t* r, uint32_t addr) {
    asm volatile("ldmatrix.sync.aligned.m8n8.x4.shared.b16 {%0,%1,%2,%3}, [%4];"
                 : "=r"(r[0]), "=r"(r[1]), "=r"(r[2]), "=r"(r[3]) : "r"(addr));
}
__device__ __forceinline__ void ldsm_x2(uint32_t* r, uint32_t addr) {
    asm volatile("ldmatrix.sync.aligned.m8n8.x2.shared.b16 {%0,%1}, [%2];"
                 : "=r"(r[0]), "=r"(r[1]) : "r"(addr));
}
__device__ __forceinline__ void mma_bf16(float* d, const uint32_t* a, const uint32_t* b) {
    asm volatile(
        "mma.sync.aligned.m16n8k16.row.col.f32.bf16.bf16.f32 "
        "{%0,%1,%2,%3}, {%4,%5,%6,%7}, {%8,%9}, {%0,%1,%2,%3};"
        : "+f"(d[0]), "+f"(d[1]), "+f"(d[2]), "+f"(d[3])
        : "r"(a[0]), "r"(a[1]), "r"(a[2]), "r"(a[3]), "r"(b[0]), "r"(b[1]));
}
// order-preserving uint16 key of a float (via bf16)
__device__ __forceinline__ uint16_t bf16_mono(float x) {
    __nv_bfloat16 b = __float2bfloat16(x);
    uint16_t u;
    memcpy(&u, &b, 2);
    return (u & 0x8000) ? (uint16_t)(~u) : (uint16_t)(u | 0x8000);
}

// ================= HMMA NT GEMM =================
// NPROD products; NTILE=128/64; fp32/key16 out; CAUSAL: 0=none,
// 1=skip fully-masked tiles (n0 >= m0+128), 2=clamp K to m0+128 (A rows zero beyond).
static constexpr int kRowB = 80;            // bytes per smem row (conflict-free ldmatrix)
static constexpr int kAMat = 128 * kRowB;   // 10240 (A tile always 128 rows)

template<int NPROD, bool KEY16, int NTILE, int CAUSAL>
__global__ void __launch_bounds__(256, (NTILE == 64) ? 2 : 1)
mma_gemm(const __nv_bfloat16* __restrict__ Ah, const __nv_bfloat16* __restrict__ Al,
         const __nv_bfloat16* __restrict__ Bh, const __nv_bfloat16* __restrict__ Bl,
         void* __restrict__ Cv,
         int lda, int ldb, int ldc,
         long long aS, long long bS, long long cS, int K)
{
    constexpr int kBMat = NTILE * kRowB;
    constexpr int AH = 0;
    constexpr int AL = kAMat;                                   // used if NPROD==3
    constexpr int BH = (NPROD == 3) ? 2 * kAMat : kAMat;
    constexpr int BL = BH + kBMat;
    constexpr int STAGE = ((NPROD == 3) ? 2 * kAMat : kAMat) + ((NPROD == 3) ? 2 : 1) * kBMat;

    constexpr int WY = (NTILE == 128) ? 2 : 4;   // warp rows
    constexpr int WX = 8 / WY;                   // warp cols
    constexpr int WM = 128 / WY;                 // rows per warp
    constexpr int WN = NTILE / WX;               // cols per warp
    constexpr int NI = WM / 16;                  // m16 frags
    constexpr int NJ = WN / 8;                   // n8 frags

    extern __shared__ char smem[];
    const uint32_t sb = smem_u32(smem);
    const int tid  = threadIdx.x;
    const int lane = tid & 31;
    const int warp = tid >> 5;
    const int wy = (NTILE == 128) ? (warp >> 2) : (warp >> 1);
    const int wx = (NTILE == 128) ? (warp & 3)  : (warp & 1);
    const int m0 = blockIdx.y * 128, n0 = blockIdx.x * NTILE, z = blockIdx.z;

    // fully-masked QK tile: output never read downstream
    if (CAUSAL == 1 && n0 >= m0 + 128) return;

    const __nv_bfloat16* pAh = Ah + (long long)z * aS;
    const __nv_bfloat16* pAl = (NPROD == 3) ? Al + (long long)z * aS : nullptr;
    const __nv_bfloat16* pBh = Bh + (long long)z * bS;
    const __nv_bfloat16* pBl = (NPROD == 3) ? Bl + (long long)z * bS : nullptr;

    float acc[NI][NJ][4];
#pragma unroll
    for (int i = 0; i < NI; i++)
#pragma unroll
        for (int j = 0; j < NJ; j++)
#pragma unroll
            for (int e = 0; e < 4; e++) acc[i][j][e] = 0.f;

    // CAUSAL==2: A columns >= m0+128 are exactly zero (P triangular), fma(0,b,acc)==acc
    const int nCh = (CAUSAL == 2) ? min(K >> 5, (m0 + 128) >> 5) : (K >> 5);

    auto stageStore = [&](int c) {
        const int k0 = c << 5;
        char* stp = smem + (c & 1) * STAGE;
#pragma unroll
        for (int u = tid; u < 512; u += 256) {
            const int r = u >> 2, cc = u & 3;
            const long long ga = (long long)(m0 + r) * lda + k0 + cc * 8;
            const int so = r * kRowB + cc * 16;
            *(uint4*)(stp + AH + so) = *(const uint4*)(pAh + ga);
            if (NPROD == 3) *(uint4*)(stp + AL + so) = *(const uint4*)(pAl + ga);
        }
#pragma unroll
        for (int u = tid; u < NTILE * 4; u += 256) {
            const int r = u >> 2, cc = u & 3;
            const long long gb = (long long)(n0 + r) * ldb + k0 + cc * 8;
            const int so = r * kRowB + cc * 16;
            *(uint4*)(stp + BH + so) = *(const uint4*)(pBh + gb);
            if (NPROD == 3) *(uint4*)(stp + BL + so) = *(const uint4*)(pBl + gb);
        }
    };

    stageStore(0);
    __syncthreads();

    const int laneA_row = (lane & 15);
    const int laneA_cb  = (lane >> 4) * 16;
    const int laneB_row = (lane & 7);
    const int laneB_cb  = ((lane >> 3) & 1) * 16;

    for (int c = 0; c < nCh; c++) {
        if (c + 1 < nCh) stageStore(c + 1);

        const uint32_t stb = sb + (c & 1) * STAGE;
#pragma unroll
        for (int kf = 0; kf < 2; kf++) {
            const int kb = kf * 32;
            uint32_t a_h[NI][4], a_l[NI][4], b_h[NJ][2], b_l[NJ][2];
#pragma unroll
            for (int i = 0; i < NI; i++) {
                const uint32_t ra = stb + (uint32_t)((wy * WM + i * 16 + laneA_row) * kRowB + kb + laneA_cb);
                ldsm_x4(a_h[i], ra + AH);
                if (NPROD == 3) ldsm_x4(a_l[i], ra + AL);
            }
#pragma unroll
            for (int j = 0; j < NJ; j++) {
                const uint32_t rb = stb + (uint32_t)((wx * WN + j * 8 + laneB_row) * kRowB + kb + laneB_cb);
                ldsm_x2(b_h[j], rb + BH);
                if (NPROD == 3) ldsm_x2(b_l[j], rb + BL);
            }
#pragma unroll
            for (int i = 0; i < NI; i++)
#pragma unroll
                for (int j = 0; j < NJ; j++) {
                    mma_bf16(acc[i][j], a_h[i], b_h[j]);
                    if (NPROD == 3) {
                        mma_bf16(acc[i][j], a_h[i], b_l[j]);
                        mma_bf16(acc[i][j], a_l[i], b_h[j]);
                    }
                }
        }
        __syncthreads();
    }

    if (KEY16) {
        uint16_t* Cb = (uint16_t*)Cv + (long long)z * cS;
#pragma unroll
        for (int i = 0; i < NI; i++) {
            const int rr = m0 + wy * WM + i * 16 + (lane >> 2);
#pragma unroll
            for (int j = 0; j < NJ; j++) {
                const int cc = n0 + wx * WN + j * 8 + (lane & 3) * 2;
                const uint32_t k0 = (uint32_t)bf16_mono(acc[i][j][0]) | ((uint32_t)bf16_mono(acc[i][j][1]) << 16);
                const uint32_t k1 = (uint32_t)bf16_mono(acc[i][j][2]) | ((uint32_t)bf16_mono(acc[i][j][3]) << 16);
                *(uint32_t*)(Cb + (long long)rr * ldc + cc)       = k0;
                *(uint32_t*)(Cb + (long long)(rr + 8) * ldc + cc) = k1;
            }
        }
    } else {
        float* Cb = (float*)Cv + (long long)z * cS;
#pragma unroll
        for (int i = 0; i < NI; i++) {
            const int rr = m0 + wy * WM + i * 16 + (lane >> 2);
#pragma unroll
            for (int j = 0; j < NJ; j++) {
                const int cc = n0 + wx * WN + j * 8 + (lane & 3) * 2;
                float2 v0; v0.x = acc[i][j][0]; v0.y = acc[i][j][1];
                float2 v1; v1.x = acc[i][j][2]; v1.y = acc[i][j][3];
                *(float2*)(Cb + (long long)rr * ldc + cc)       = v0;
                *(float2*)(Cb + (long long)(rr + 8) * ldc + cc) = v1;
            }
        }
    }
}

static constexpr int kSmem3_128 = 2 * (4 * kAMat);                    // 81920
static constexpr int kSmem3_64  = 2 * (2 * kAMat + 2 * 64 * kRowB);   // 61440
static constexpr int kSmem1_128 = 2 * (2 * kAMat);                    // 40960

// ================= fp32 SGEMM 64x128 tile (exact path for Q projection) ==========
__global__ void __launch_bounds__(256, 2)
sgemm_nt(const float* __restrict__ A, int lda,
         const float* __restrict__ B, int ldb,
         float* __restrict__ C, int ldc, int K)
{
    __shared__ float As[16][64];
    __shared__ float Bs[16][128];

    const int tid = threadIdx.x;
    const int m0  = blockIdx.y * 64;
    const int n0  = blockIdx.x * 128;

    const int lr = tid >> 2;
    const int lc = (tid & 3) << 2;
    const int tx = tid & 15;
    const int ty = tid >> 4;

    float acc[4][8];
#pragma unroll
    for (int i = 0; i < 4; i++)
#pragma unroll
        for (int j = 0; j < 8; j++) acc[i][j] = 0.f;

    for (int k0 = 0; k0 < K; k0 += 16) {
        float4 a0 = *(const float4*)(A + (long long)(m0 + lr)      * lda + k0 + lc);
        float4 b0 = *(const float4*)(B + (long long)(n0 + lr)      * ldb + k0 + lc);
        float4 b1 = *(const float4*)(B + (long long)(n0 + lr + 64) * ldb + k0 + lc);
        __syncthreads();
        As[lc + 0][lr] = a0.x; As[lc + 1][lr] = a0.y; As[lc + 2][lr] = a0.z; As[lc + 3][lr] = a0.w;
        Bs[lc + 0][lr] = b0.x; Bs[lc + 1][lr] = b0.y; Bs[lc + 2][lr] = b0.z; Bs[lc + 3][lr] = b0.w;
        Bs[lc + 0][lr + 64] = b1.x; Bs[lc + 1][lr + 64] = b1.y; Bs[lc + 2][lr + 64] = b1.z; Bs[lc + 3][lr + 64] = b1.w;
        __syncthreads();
#pragma unroll
        for (int kk = 0; kk < 16; kk++) {
            float4 av = *(const float4*)&As[kk][ty * 4];
            float4 bv0 = *(const float4*)&Bs[kk][tx * 8];
            float4 bv1 = *(const float4*)&Bs[kk][tx * 8 + 4];
            float a[4] = {av.x, av.y, av.z, av.w};
            float b[8] = {bv0.x, bv0.y, bv0.z, bv0.w, bv1.x, bv1.y, bv1.z, bv1.w};
#pragma unroll
            for (int i = 0; i < 4; i++)
#pragma unroll
                for (int j = 0; j < 8; j++) acc[i][j] = fmaf(a[i], b[j], acc[i][j]);
        }
    }

#pragma unroll
    for (int i = 0; i < 4; i++) {
        float* crow = C + (long long)(m0 + ty * 4 + i) * ldc + n0 + tx * 8;
#pragma unroll
        for (int j = 0; j < 8; j++) crow[j] = acc[i][j];
    }
}

// ================= splits =================
__global__ void split_kernel(const float* __restrict__ src,
                             __nv_bfloat16* __restrict__ hi,
                             __nv_bfloat16* __restrict__ lo, int n4)
{
    const int i = blockIdx.x * blockDim.x + threadIdx.x;
    if (i >= n4) return;
    const float4 v = ((const float4*)src)[i];
    __nv_bfloat16 h0 = __float2bfloat16(v.x);
    __nv_bfloat16 h1 = __float2bfloat16(v.y);
    __nv_bfloat16 h2 = __float2bfloat16(v.z);
    __nv_bfloat16 h3 = __float2bfloat16(v.w);
    __nv_bfloat162 H0; H0.x = h0; H0.y = h1;
    __nv_bfloat162 H1; H1.x = h2; H1.y = h3;
    __nv_bfloat162 L0, L1;
    L0.x = __float2bfloat16(v.x - __bfloat162float(h0));
    L0.y = __float2bfloat16(v.y - __bfloat162float(h1));
    L1.x = __float2bfloat16(v.z - __bfloat162float(h2));
    L1.y = __float2bfloat16(v.w - __bfloat162float(h3));
    ((__nv_bfloat162*)hi)[2 * i]     = H0;
    ((__nv_bfloat162*)hi)[2 * i + 1] = H1;
    ((__nv_bfloat162*)lo)[2 * i]     = L0;
    ((__nv_bfloat162*)lo)[2 * i + 1] = L1;
}

// sum of two fp32 buffers -> bf16 hi/lo split
__global__ void sumsplit_kernel(const float* __restrict__ a, const float* __restrict__ b,
                                __nv_bfloat16* __restrict__ hi,
                                __nv_bfloat16* __restrict__ lo, int n4)
{
    const int i = blockIdx.x * blockDim.x + threadIdx.x;
    if (i >= n4) return;
    const float4 va = ((const float4*)a)[i];
    const float4 vb = ((const float4*)b)[i];
    float4 v;
    v.x = va.x + vb.x; v.y = va.y + vb.y; v.z = va.z + vb.z; v.w = va.w + vb.w;
    __nv_bfloat16 h0 = __float2bfloat16(v.x);
    __nv_bfloat16 h1 = __float2bfloat16(v.y);
    __nv_bfloat16 h2 = __float2bfloat16(v.z);
    __nv_bfloat16 h3 = __float2bfloat16(v.w);
    __nv_bfloat162 H0; H0.x = h0; H0.y = h1;
    __nv_bfloat162 H1; H1.x = h2; H1.y = h3;
    __nv_bfloat162 L0, L1;
    L0.x = __float2bfloat16(v.x - __bfloat162float(h0));
    L0.y = __float2bfloat16(v.y - __bfloat162float(h1));
    L1.x = __float2bfloat16(v.z - __bfloat162float(h2));
    L1.y = __float2bfloat16(v.w - __bfloat162float(h3));
    ((__nv_bfloat162*)hi)[2 * i]     = H0;
    ((__nv_bfloat162*)hi)[2 * i + 1] = H1;
    ((__nv_bfloat162*)lo)[2 * i]     = L0;
    ((__nv_bfloat162*)lo)[2 * i + 1] = L1;
}

// strided split of g_qkv columns [0,4096) (local Q|K) -> g_lqk hi/lo [512 x 4096]
__global__ void qksplit_kernel()
{
    const int i = blockIdx.x * blockDim.x + threadIdx.x;   // over 512*1024 float4
    if (i >= kS * 1024) return;
    const int row = i >> 10;
    const int c4  = (i & 1023) << 2;
    const float4 v = *(const float4*)&g_qkv[(long long)row * kQKVld + c4];
    __nv_bfloat16 h0 = __float2bfloat16(v.x);
    __nv_bfloat16 h1 = __float2bfloat16(v.y);
    __nv_bfloat16 h2 = __float2bfloat16(v.z);
    __nv_bfloat16 h3 = __float2bfloat16(v.w);
    __nv_bfloat162 H0; H0.x = h0; H0.y = h1;
    __nv_bfloat162 H1; H1.x = h2; H1.y = h3;
    __nv_bfloat162 L0, L1;
    L0.x = __float2bfloat16(v.x - __bfloat162float(h0));
    L0.y = __float2bfloat16(v.y - __bfloat162float(h1));
    L1.x = __float2bfloat16(v.z - __bfloat162float(h2));
    L1.y = __float2bfloat16(v.w - __bfloat162float(h3));
    ((__nv_bfloat162*)g_lqk_h)[2 * i]     = H0;
    ((__nv_bfloat162*)g_lqk_h)[2 * i + 1] = H1;
    ((__nv_bfloat162*)g_lqk_l)[2 * i]     = L0;
    ((__nv_bfloat162*)g_lqk_l)[2 * i + 1] = L1;
}

// V local transpose + split: g_qkv V part [k][h*128+d] -> g_vT [h][d][k] bf16 hi/lo
__global__ void vtrans_kernel()
{
    __shared__ float t[32][33];
    const int h  = blockIdx.z;
    const int dt = blockIdx.y;
    const int kt = blockIdx.x;
    const int tx = threadIdx.x & 31;
    const int ty = threadIdx.x >> 5;   // 0..7
#pragma unroll
    for (int i = 0; i < 4; i++) {
        const int k = kt * 32 + ty + i * 8;
        t[ty + i * 8][tx] = g_qkv[(long long)k * kQKVld + 2 * kH + h * kD + dt * 32 + tx];
    }
    __syncthreads();
#pragma unroll
    for (int i = 0; i < 4; i++) {
        const int d = dt * 32 + ty + i * 8;
        const float val = t[tx][ty + i * 8];
        const long long o = ((long long)h * kD + d) * kS + kt * 32 + tx;
        const __nv_bfloat16 hi = __float2bfloat16(val);
        g_vT_h[o] = hi;
        g_vT_l[o] = __float2bfloat16(val - __bfloat162float(hi));
    }
}

__global__ void qsplit_kernel()
{
    const int gw   = (blockIdx.x * blockDim.x + threadIdx.x) >> 5;
    const int lane = threadIdx.x & 31;
    if (gw >= kNH * kS) return;
    const int h = gw >> 9;
    const int q = gw & 511;
    float4 v = *(const float4*)(g_qkv + (long long)q * kQKVld + h * kD + lane * 4);
    float s = v.x * v.x + v.y * v.y + v.z * v.z + v.w * v.w;
#pragma unroll
    for (int o = 16; o > 0; o >>= 1) s += __shfl_xor_sync(0xffffffffu, s, o);
    const float inv = rsqrtf(s);
    v.x *= inv; v.y *= inv; v.z *= inv; v.w *= inv;
    const long long base = (long long)gw * kD + lane * 4;
    *(float4*)(g_qn_f32 + base) = v;
    __nv_bfloat162 H0, H1;
    H0.x = __float2bfloat16(v.x); H0.y = __float2bfloat16(v.y);
    H1.x = __float2bfloat16(v.z); H1.y = __float2bfloat16(v.w);
    *(__nv_bfloat162*)(g_qn_h + base)     = H0;
    *(__nv_bfloat162*)(g_qn_h + base + 2) = H1;
}

__global__ void ksplit_kernel(const float* __restrict__ kc)
{
    const int gw   = (blockIdx.x * blockDim.x + threadIdx.x) >> 5;
    const int lane = threadIdx.x & 31;
    if (gw >= kNH * kSC) return;
    float4 v = *(const float4*)(kc + (long long)gw * kD + lane * 4);
    float s = v.x * v.x + v.y * v.y + v.z * v.z + v.w * v.w;
#pragma unroll
    for (int o = 16; o > 0; o >>= 1) s += __shfl_xor_sync(0xffffffffu, s, o);
    const float inv = rsqrtf(s);
    v.x *= inv; v.y *= inv; v.z *= inv; v.w *= inv;
    const long long base = (long long)gw * kD + lane * 4;
    *(float4*)(g_kn_f32 + base) = v;
    __nv_bfloat162 H0, H1;
    H0.x = __float2bfloat16(v.x); H0.y = __float2bfloat16(v.y);
    H1.x = __float2bfloat16(v.z); H1.y = __float2bfloat16(v.w);
    *(__nv_bfloat162*)(g_kn_h + base)     = H0;
    *(__nv_bfloat162*)(g_kn_h + base + 2) = H1;
}

// ---------------- per-(h,q) approx top-32 over 8192 packed keys ----------------
// R13 block tournament (proven): packed = key16 << 13 | (8191 - idx).
__global__ void __launch_bounds__(256)
topk_kernel()
{
    const long long row = blockIdx.x;  // h*512 + q
    const uint16_t* sim = g_simkey + row * kSC;
    const int tid = threadIdx.x;
    const int lane = tid & 31;
    const int w = tid >> 5;

    uint32_t v[32];
#pragma unroll
    for (int c = 0; c < 4; c++) {
        const int base = c * 2048 + tid * 8;
        uint4 raw = *(const uint4*)(sim + base);
        const uint32_t words[4] = {raw.x, raw.y, raw.z, raw.w};
#pragma unroll
        for (int j = 0; j < 4; j++) {
            const uint32_t lo = words[j] & 0xFFFFu;
            const uint32_t hi = words[j] >> 16;
            v[c * 8 + 2 * j]     = (lo << 13) | (uint32_t)(8191 - (base + 2 * j));
            v[c * 8 + 2 * j + 1] = (hi << 13) | (uint32_t)(8191 - (base + 2 * j + 1));
        }
    }

    uint32_t locmax = 0;
#pragma unroll
    for (int i = 0; i < 32; i++) locmax = max(locmax, v[i]);

    __shared__ uint32_t wv[8];
    __shared__ uint32_t bshare;

    for (int r = 0; r < kCand; r++) {
        const uint32_t wm = __reduce_max_sync(0xffffffffu, locmax);
        if (lane == 0) wv[w] = wm;
        __syncthreads();
        if (tid == 0) {
            uint32_t b = wv[0];
#pragma unroll
            for (int k = 1; k < 8; k++) b = max(b, wv[k]);
            bshare = b;
            g_cand[row * kCand + r] = 8191 - (int)(b & 8191u);
        }
        __syncthreads();
        const uint32_t best = bshare;
        if (locmax == best) {
            uint32_t nm = 0;
#pragma unroll
            for (int i = 0; i < 32; i++) {
                if (v[i] == best) v[i] = 0;
                nm = max(nm, v[i]);
            }
            locmax = nm;
        }
    }
}

// ---------------- exact rescore of 32 candidates -> exact top-16 ----------------
__global__ void __launch_bounds__(256)
rescore_kernel()
{
    const int gw   = (blockIdx.x * blockDim.x + threadIdx.x) >> 5;
    const int lane = threadIdx.x & 31;
    if (gw >= kNH * kS) return;
    const int h = gw >> 9;

    const float4 qv = *(const float4*)(g_qn_f32 + (long long)gw * kD + lane * 4);
    int   myidx = g_cand[gw * kCand + lane];
    float myval = -FLT_MAX;

    for (int c = 0; c < kCand; c++) {
        const int idx = __shfl_sync(0xffffffffu, myidx, c);
        const float4 kv = *(const float4*)(g_kn_f32 + ((long long)h * kSC + idx) * kD + lane * 4);
        float p = qv.x * kv.x + qv.y * kv.y + qv.z * kv.z + qv.w * kv.w;
#pragma unroll
        for (int o = 16; o > 0; o >>= 1) p += __shfl_xor_sync(0xffffffffu, p, o);
        if (lane == c) myval = p;
    }

    for (int r = 0; r < kTopK; r++) {
        float v = myval; int ix = myidx;
#pragma unroll
        for (int o = 16; o > 0; o >>= 1) {
            float ov = __shfl_xor_sync(0xffffffffu, v, o);
            int   oi = __shfl_xor_sync(0xffffffffu, ix, o);
            if (ov > v || (ov == v && oi < ix)) { v = ov; ix = oi; }
        }
        if (lane == 0) {
            g_topv[gw * kTopK + r] = v;
            g_topi[gw * kTopK + r] = ix;
        }
        if (myidx == ix) myval = -FLT_MAX;
    }
}

// ---------------- softmax + ext context per (h,q) ----------------
__global__ void __launch_bounds__(256)
softmax_kernel(const float* __restrict__ kc, const float* __restrict__ vc,
               const float* __restrict__ bias)
{
    const int q = blockIdx.x;
    const int h = blockIdx.y;
    const int tid = threadIdx.x;
    const int lane = tid & 31;
    const int w = tid >> 5;

    __shared__ float qs[128];
    __shared__ float ssc[16 + kS];
    __shared__ int   sidx[16];
    __shared__ float redw[8];
    __shared__ float bmax, bsuminv;

    const long long rowhq = (long long)h * kS + q;

    if (tid < 128) qs[tid] = g_qkv[(long long)q * kQKVld + h * kD + tid];
    if (tid < 16)  sidx[tid] = g_topi[rowhq * 16 + tid];
    __syncthreads();

    const float4 qv = *(const float4*)(qs + lane * 4);

    for (int j = w; j < 16; j += 8) {
        float s;
        if (g_topv[rowhq * 16 + j] > kSimTh) {
            const float* kp = kc + ((long long)h * kSC + sidx[j]) * kD;
            float4 kv = *(const float4*)(kp + lane * 4);
            float p = qv.x * kv.x + qv.y * kv.y + qv.z * kv.z + qv.w * kv.w;
#pragma unroll
            for (int o = 16; o > 0; o >>= 1) p += __shfl_down_sync(0xffffffffu, p, o);
            s = p * kScale;
        } else {
            s = kNeg;
        }
        if (lane == 0) ssc[j] = s;
    }

    const float* srow  = g_scores + rowhq * kS;
    const float* brow  = bias + rowhq * kS;
    for (int j = tid; j < kS; j += 256) {
        ssc[16 + j] = (j <= q) ? srow[j] * kScale + brow[j] : kNeg;
    }
    __syncthreads();

    float m = -FLT_MAX;
    for (int j = tid; j < 16 + kS; j += 256) m = fmaxf(m, ssc[j]);
#pragma unroll
    for (int o = 16; o > 0; o >>= 1) m = fmaxf(m, __shfl_down_sync(0xffffffffu, m, o));
    if (lane == 0) redw[w] = m;
    __syncthreads();
    if (tid == 0) {
        float mm = redw[0];
#pragma unroll
        for (int k = 1; k < 8; k++) mm = fmaxf(mm, redw[k]);
        bmax = mm;
    }
    __syncthreads();
    const float msc = bmax;
    float ss = 0.f;
    for (int j = tid; j < 16 + kS; j += 256) {
        float e = __expf(ssc[j] - msc);
        ssc[j] = e;
        ss += e;
    }
#pragma unroll
    for (int o = 16; o > 0; o >>= 1) ss += __shfl_down_sync(0xffffffffu, ss, o);
    if (lane == 0) redw[w] = ss;
    __syncthreads();
    if (tid == 0) {
        float t = 0.f;
#pragma unroll
        for (int k = 0; k < 8; k++) t += redw[k];
        bsuminv = 1.f / t;
    }
    __syncthreads();
    const float inv = bsuminv;

    for (int j = tid; j < kS; j += 256) {
        const float p = ssc[16 + j] * inv;
        const __nv_bfloat16 hi = __float2bfloat16(p);
        g_pl_h[rowhq * kS + j] = hi;
        g_pl_l[rowhq * kS + j] = __float2bfloat16(p - __bfloat162float(hi));
    }

    if (tid < 128) {
        float acc = 0.f;
        for (int j = 0; j < 16; j++) {
            const float p = ssc[j] * inv;
            if (p > 0.f) acc += p * vc[((long long)h * kSC + sidx[j]) * kD + tid];
        }
        g_ctxe[(long long)q * kH + h * kD + tid] = acc;
    }
}

// ---------------- launcher ----------------
extern "C" void kernel_launch(void* const* d_in, const int* in_sizes, int n_in,
                              void* d_out, int out_size)
{
    const float* hidden = (const float*)d_in[0];
    const float* Wqkv   = (const float*)d_in[1];
    const float* Wout   = (const float*)d_in[2];
    const float* kc     = (const float*)d_in[3];
    const float* vc     = (const float*)d_in[4];
    const float* bias   = (const float*)d_in[5];
    float* out = (float*)d_out;

    float *p_qkv, *p_scores, *p_ctxe, *p_ctxl;
    uint16_t* p_simkey;
    cudaGetSymbolAddress((void**)&p_qkv,    g_qkv);
    cudaGetSymbolAddress((void**)&p_simkey, g_simkey);
    cudaGetSymbolAddress((void**)&p_scores, g_scores);
    cudaGetSymbolAddress((void**)&p_ctxe,   g_ctxe);
    cudaGetSymbolAddress((void**)&p_ctxl,   g_ctxl);
    __nv_bfloat16 *p_hid_h, *p_hid_l, *p_wqkv_h, *p_wqkv_l, *p_wout_h, *p_wout_l;
    __nv_bfloat16 *p_qn_h, *p_kn_h, *p_ctx_h, *p_ctx_l;
    __nv_bfloat16 *p_lqk_h, *p_lqk_l, *p_vT_h, *p_vT_l, *p_pl_h, *p_pl_l;
    cudaGetSymbolAddress((void**)&p_hid_h,  g_hid_h);
    cudaGetSymbolAddress((void**)&p_hid_l,  g_hid_l);
    cudaGetSymbolAddress((void**)&p_wqkv_h, g_wqkv_h);
    cudaGetSymbolAddress((void**)&p_wqkv_l, g_wqkv_l);
    cudaGetSymbolAddress((void**)&p_wout_h, g_wout_h);
    cudaGetSymbolAddress((void**)&p_wout_l, g_wout_l);
    cudaGetSymbolAddress((void**)&p_qn_h,   g_qn_h);
    cudaGetSymbolAddress((void**)&p_kn_h,   g_kn_h);
    cudaGetSymbolAddress((void**)&p_ctx_h,  g_ctx_h);
    cudaGetSymbolAddress((void**)&p_ctx_l,  g_ctx_l);
    cudaGetSymbolAddress((void**)&p_lqk_h,  g_lqk_h);
    cudaGetSymbolAddress((void**)&p_lqk_l,  g_lqk_l);
    cudaGetSymbolAddress((void**)&p_vT_h,   g_vT_h);
    cudaGetSymbolAddress((void**)&p_vT_l,   g_vT_l);
    cudaGetSymbolAddress((void**)&p_pl_h,   g_pl_h);
    cudaGetSymbolAddress((void**)&p_pl_l,   g_pl_l);

    cudaFuncSetAttribute((const void*)mma_gemm<3, false, 128, 1>, cudaFuncAttributeMaxDynamicSharedMemorySize, kSmem3_128);
    cudaFuncSetAttribute((const void*)mma_gemm<3, false, 64, 0>,  cudaFuncAttributeMaxDynamicSharedMemorySize, kSmem3_64);
    cudaFuncSetAttribute((const void*)mma_gemm<3, false, 64, 2>,  cudaFuncAttributeMaxDynamicSharedMemorySize, kSmem3_64);
    cudaFuncSetAttribute((const void*)mma_gemm<1, true, 128, 0>,  cudaFuncAttributeMaxDynamicSharedMemorySize, kSmem1_128);

    // ---- selection chain first (sim mma = launch #3 for ncu visibility) ----
    ksplit_kernel<<<(kNH * kSC * 32) / 256, 256>>>(kc);
    sgemm_nt<<<dim3(kH / 128, kS / 64), 256>>>(hidden, kH, Wqkv, kH, p_qkv, kQKVld, kH);
    qsplit_kernel<<<(kNH * kS * 32) / 256, 256>>>();
    mma_gemm<1, true, 128, 0><<<dim3(kSC / 128, kS / 128, kNH), 256, kSmem1_128>>>(
        p_qn_h, nullptr, p_kn_h, nullptr, p_simkey,
        kD, kD, kSC,
        (long long)kS * kD, (long long)kSC * kD, (long long)kS * kSC, kD);
    topk_kernel<<<kNH * kS, 256>>>();
    rescore_kernel<<<(kNH * kS * 32 + 255) / 256, 256>>>();

    // ---- projection / attention chain ----
    split_kernel<<<(4096 * kH / 4 + 255) / 256, 256>>>(Wqkv + (size_t)2048 * kH, p_wqkv_h, p_wqkv_l, 4096 * kH / 4);
    split_kernel<<<(kS * kH / 4 + 255) / 256, 256>>>(hidden, p_hid_h, p_hid_l, kS * kH / 4);
    mma_gemm<3, false, 64, 0><<<dim3(4096 / 64, kS / 128, 1), 256, kSmem3_64>>>(
        p_hid_h, p_hid_l, p_wqkv_h, p_wqkv_l,
        p_qkv + 2048, kH, kH, kQKVld, 0, 0, 0, kH);

    // local QK^T (causal: skip fully-masked upper tiles — outputs never read)
    qksplit_kernel<<<(kS * 1024 + 255) / 256, 256>>>();
    mma_gemm<3, false, 128, 1><<<dim3(kS / 128, kS / 128, kNH), 256, kSmem3_128>>>(
        p_lqk_h, p_lqk_l, p_lqk_h + 2048, p_lqk_l + 2048,
        p_scores, 4096, 4096, kS,
        128, 128, (long long)kS * kS, kD);

    vtrans_kernel<<<dim3(kS / 32, kD / 32, kNH), 256>>>();

    softmax_kernel<<<dim3(kS, kNH), 256>>>(kc, vc, bias);

    // local PV (causal: clamp K to m0+128 — skipped P columns are exactly zero)
    mma_gemm<3, false, 64, 2><<<dim3(kD / 64, kS / 128, kNH), 256, kSmem3_64>>>(
        p_pl_h, p_pl_l, p_vT_h, p_vT_l,
        p_ctxl, kS, kS, kH,
        (long long)kS * kS, (long long)kD * kS, 128, kS);

    split_kernel<<<(kH * kH / 4 + 255) / 256, 256>>>(Wout, p_wout_h, p_wout_l, kH * kH / 4);
    sumsplit_kernel<<<(kS * kH / 4 + 255) / 256, 256>>>(p_ctxl, p_ctxe, p_ctx_h, p_ctx_l, kS * kH / 4);
    mma_gemm<3, false, 64, 0><<<dim3(kH / 64, kS / 128, 1), 256, kSmem3_64>>>(
        p_ctx_h, p_ctx_l, p_wout_h, p_wout_l, out,
        kH, kH, kH, 0, 0, 0, kH);
}

// round 16
// speedup vs baseline: 1.2428x; 1.0612x over previous
#include <cuda_runtime.h>
#include <cuda_bf16.h>
#include <cfloat>
#include <math.h>
#include <stdint.h>
#include <string.h>

// ---------------- problem constants ----------------
static constexpr int kNH   = 16;
static constexpr int kS    = 512;
static constexpr int kH    = 2048;
static constexpr int kD    = 128;
static constexpr int kSC   = 8192;   // cache length
static constexpr int kTopK = 16;
static constexpr int kCand = 32;     // approx candidate pool per row
static constexpr int kQKVld = 3 * kH;          // 6144
static constexpr float kScale = 0.08838834764831845f;  // 1/sqrt(128)
static constexpr float kSimTh = 0.25f;
static constexpr float kNeg   = -1e30f;

// ---------------- scratch (__device__ globals; no allocation allowed) ----------------
__device__ __align__(16) float g_qkv[kS * kQKVld];                    // 12.6 MB
__device__ __align__(16) uint16_t g_simkey[(size_t)kNH * kS * kSC];   // 134 MB monotone keys
__device__ float g_topv[kNH * kS * kTopK];                            // exact vals
__device__ int   g_topi[kNH * kS * kTopK];                            // exact top-16 idx
__device__ int   g_cand[kNH * kS * kCand];                            // approx top-32 pool
__device__ __align__(16) float g_qn_f32[kNH * kS * kD];               // normalized q fp32
__device__ __align__(16) float g_kn_f32[(size_t)kNH * kSC * kD];      // normalized k fp32

// attention pipeline buffers
__device__ __align__(16) float g_scores[(size_t)kNH * kS * kS];       // 16.8 MB raw QK^T
__device__ __align__(16) float g_ctxe[kS * kH];                       // ext context
__device__ __align__(16) float g_ctxl[kS * kH];                       // local context

// bf16 operands
__device__ __align__(16) __nv_bfloat16 g_hid_h[kS * kH];
__device__ __align__(16) __nv_bfloat16 g_hid_l[kS * kH];
__device__ __align__(16) __nv_bfloat16 g_wqkv_h[kQKVld * kH];
__device__ __align__(16) __nv_bfloat16 g_wqkv_l[kQKVld * kH];
__device__ __align__(16) __nv_bfloat16 g_wout_h[kH * kH];
__device__ __align__(16) __nv_bfloat16 g_wout_l[kH * kH];
__device__ __align__(16) __nv_bfloat16 g_qn_h[kNH * kS * kD];
__device__ __align__(16) __nv_bfloat16 g_kn_h[kNH * kSC * kD];
__device__ __align__(16) __nv_bfloat16 g_ctx_h[kS * kH];
__device__ __align__(16) __nv_bfloat16 g_ctx_l[kS * kH];
__device__ __align__(16) __nv_bfloat16 g_lqk_h[kS * 4096];            // local Q|K bf16 hi
__device__ __align__(16) __nv_bfloat16 g_lqk_l[kS * 4096];            // local Q|K bf16 lo
__device__ __align__(16) __nv_bfloat16 g_vT_h[kNH * kD * kS];         // V^T bf16 hi
__device__ __align__(16) __nv_bfloat16 g_vT_l[kNH * kD * kS];         // V^T bf16 lo
__device__ __align__(16) __nv_bfloat16 g_pl_h[(size_t)kNH * kS * kS]; // P bf16 hi
__device__ __align__(16) __nv_bfloat16 g_pl_l[(size_t)kNH * kS * kS]; // P bf16 lo

// ================= warp-mma helpers (compute_103-safe: sm_80 mma.sync) ==========
__device__ __forceinline__ uint32_t smem_u32(const void* p) {
    uint32_t a;
    asm("{ .reg .u64 t; cvta.to.shared.u64 t, %1; cvt.u32.u64 %0, t; }" : "=r"(a) : "l"(p));
    return a;
}
__device__ __forceinline__ void ldsm_x4(uint32_t* r, uint32_t addr) {
    asm volatile("ldmatrix.sync.aligned.m8n8.x4.shared.b16 {%0,%1,%2,%3}, [%4];"
                 : "=r"(r[0]), "=r"(r[1]), "=r"(r[2]), "=r"(r[3]) : "r"(addr));
}
__device__ __forceinline__ void ldsm_x2(uint32_t* r, uint32_t addr) {
    asm volatile("ldmatrix.sync.aligned.m8n8.x2.shared.b16 {%0,%1}, [%2];"
                 : "=r"(r[0]), "=r"(r[1]) : "r"(addr));
}
__device__ __forceinline__ void mma_bf16(float* d, const uint32_t* a, const uint32_t* b) {
    asm volatile(
        "mma.sync.aligned.m16n8k16.row.col.f32.bf16.bf16.f32 "
        "{%0,%1,%2,%3}, {%4,%5,%6,%7}, {%8,%9}, {%0,%1,%2,%3};"
        : "+f"(d[0]), "+f"(d[1]), "+f"(d[2]), "+f"(d[3])
        : "r"(a[0]), "r"(a[1]), "r"(a[2]), "r"(a[3]), "r"(b[0]), "r"(b[1]));
}
// order-preserving uint16 key of a float (via bf16)
__device__ __forceinline__ uint16_t bf16_mono(float x) {
    __nv_bfloat16 b = __float2bfloat16(x);
    uint16_t u;
    memcpy(&u, &b, 2);
    return (u & 0x8000) ? (uint16_t)(~u) : (uint16_t)(u | 0x8000);
}

// ================= HMMA NT GEMM =================
// NPROD products; NTILE=128/64; fp32/key16 out; CAUSAL: 0=none,
// 1=skip fully-masked tiles (n0 >= m0+128), 2=clamp K to m0+128 (A rows zero beyond).
static constexpr int kRowB = 80;            // bytes per smem row (conflict-free ldmatrix)
static constexpr int kAMat = 128 * kRowB;   // 10240 (A tile always 128 rows)

template<int NPROD, bool KEY16, int NTILE, int CAUSAL>
__global__ void __launch_bounds__(256, (NTILE == 64 || NPROD == 1) ? 2 : 1)
mma_gemm(const __nv_bfloat16* __restrict__ Ah, const __nv_bfloat16* __restrict__ Al,
         const __nv_bfloat16* __restrict__ Bh, const __nv_bfloat16* __restrict__ Bl,
         void* __restrict__ Cv,
         int lda, int ldb, int ldc,
         long long aS, long long bS, long long cS, int K)
{
    constexpr int kBMat = NTILE * kRowB;
    constexpr int AH = 0;
    constexpr int AL = kAMat;                                   // used if NPROD==3
    constexpr int BH = (NPROD == 3) ? 2 * kAMat : kAMat;
    constexpr int BL = BH + kBMat;
    constexpr int STAGE = ((NPROD == 3) ? 2 * kAMat : kAMat) + ((NPROD == 3) ? 2 : 1) * kBMat;

    constexpr int WY = (NTILE == 128) ? 2 : 4;   // warp rows
    constexpr int WX = 8 / WY;                   // warp cols
    constexpr int WM = 128 / WY;                 // rows per warp
    constexpr int WN = NTILE / WX;               // cols per warp
    constexpr int NI = WM / 16;                  // m16 frags
    constexpr int NJ = WN / 8;                   // n8 frags

    extern __shared__ char smem[];
    const uint32_t sb = smem_u32(smem);
    const int tid  = threadIdx.x;
    const int lane = tid & 31;
    const int warp = tid >> 5;
    const int wy = (NTILE == 128) ? (warp >> 2) : (warp >> 1);
    const int wx = (NTILE == 128) ? (warp & 3)  : (warp & 1);
    const int m0 = blockIdx.y * 128, n0 = blockIdx.x * NTILE, z = blockIdx.z;

    // fully-masked QK tile: output never read downstream
    if (CAUSAL == 1 && n0 >= m0 + 128) return;

    const __nv_bfloat16* pAh = Ah + (long long)z * aS;
    const __nv_bfloat16* pAl = (NPROD == 3) ? Al + (long long)z * aS : nullptr;
    const __nv_bfloat16* pBh = Bh + (long long)z * bS;
    const __nv_bfloat16* pBl = (NPROD == 3) ? Bl + (long long)z * bS : nullptr;

    float acc[NI][NJ][4];
#pragma unroll
    for (int i = 0; i < NI; i++)
#pragma unroll
        for (int j = 0; j < NJ; j++)
#pragma unroll
            for (int e = 0; e < 4; e++) acc[i][j][e] = 0.f;

    // CAUSAL==2: A columns >= m0+128 are exactly zero (P triangular), fma(0,b,acc)==acc
    const int nCh = (CAUSAL == 2) ? min(K >> 5, (m0 + 128) >> 5) : (K >> 5);

    auto stageStore = [&](int c) {
        const int k0 = c << 5;
        char* stp = smem + (c & 1) * STAGE;
#pragma unroll
        for (int u = tid; u < 512; u += 256) {
            const int r = u >> 2, cc = u & 3;
            const long long ga = (long long)(m0 + r) * lda + k0 + cc * 8;
            const int so = r * kRowB + cc * 16;
            *(uint4*)(stp + AH + so) = *(const uint4*)(pAh + ga);
            if (NPROD == 3) *(uint4*)(stp + AL + so) = *(const uint4*)(pAl + ga);
        }
#pragma unroll
        for (int u = tid; u < NTILE * 4; u += 256) {
            const int r = u >> 2, cc = u & 3;
            const long long gb = (long long)(n0 + r) * ldb + k0 + cc * 8;
            const int so = r * kRowB + cc * 16;
            *(uint4*)(stp + BH + so) = *(const uint4*)(pBh + gb);
            if (NPROD == 3) *(uint4*)(stp + BL + so) = *(const uint4*)(pBl + gb);
        }
    };

    stageStore(0);
    __syncthreads();

    const int laneA_row = (lane & 15);
    const int laneA_cb  = (lane >> 4) * 16;
    const int laneB_row = (lane & 7);
    const int laneB_cb  = ((lane >> 3) & 1) * 16;

    for (int c = 0; c < nCh; c++) {
        if (c + 1 < nCh) stageStore(c + 1);

        const uint32_t stb = sb + (c & 1) * STAGE;
#pragma unroll
        for (int kf = 0; kf < 2; kf++) {
            const int kb = kf * 32;
            uint32_t a_h[NI][4], a_l[NI][4], b_h[NJ][2], b_l[NJ][2];
#pragma unroll
            for (int i = 0; i < NI; i++) {
                const uint32_t ra = stb + (uint32_t)((wy * WM + i * 16 + laneA_row) * kRowB + kb + laneA_cb);
                ldsm_x4(a_h[i], ra + AH);
                if (NPROD == 3) ldsm_x4(a_l[i], ra + AL);
            }
#pragma unroll
            for (int j = 0; j < NJ; j++) {
                const uint32_t rb = stb + (uint32_t)((wx * WN + j * 8 + laneB_row) * kRowB + kb + laneB_cb);
                ldsm_x2(b_h[j], rb + BH);
                if (NPROD == 3) ldsm_x2(b_l[j], rb + BL);
            }
#pragma unroll
            for (int i = 0; i < NI; i++)
#pragma unroll
                for (int j = 0; j < NJ; j++) {
                    mma_bf16(acc[i][j], a_h[i], b_h[j]);
                    if (NPROD == 3) {
                        mma_bf16(acc[i][j], a_h[i], b_l[j]);
                        mma_bf16(acc[i][j], a_l[i], b_h[j]);
                    }
                }
        }
        __syncthreads();
    }

    if (KEY16) {
        uint16_t* Cb = (uint16_t*)Cv + (long long)z * cS;
#pragma unroll
        for (int i = 0; i < NI; i++) {
            const int rr = m0 + wy * WM + i * 16 + (lane >> 2);
#pragma unroll
            for (int j = 0; j < NJ; j++) {
                const int cc = n0 + wx * WN + j * 8 + (lane & 3) * 2;
                const uint32_t k0 = (uint32_t)bf16_mono(acc[i][j][0]) | ((uint32_t)bf16_mono(acc[i][j][1]) << 16);
                const uint32_t k1 = (uint32_t)bf16_mono(acc[i][j][2]) | ((uint32_t)bf16_mono(acc[i][j][3]) << 16);
                *(uint32_t*)(Cb + (long long)rr * ldc + cc)       = k0;
                *(uint32_t*)(Cb + (long long)(rr + 8) * ldc + cc) = k1;
            }
        }
    } else {
        float* Cb = (float*)Cv + (long long)z * cS;
#pragma unroll
        for (int i = 0; i < NI; i++) {
            const int rr = m0 + wy * WM + i * 16 + (lane >> 2);
#pragma unroll
            for (int j = 0; j < NJ; j++) {
                const int cc = n0 + wx * WN + j * 8 + (lane & 3) * 2;
                float2 v0; v0.x = acc[i][j][0]; v0.y = acc[i][j][1];
                float2 v1; v1.x = acc[i][j][2]; v1.y = acc[i][j][3];
                *(float2*)(Cb + (long long)rr * ldc + cc)       = v0;
                *(float2*)(Cb + (long long)(rr + 8) * ldc + cc) = v1;
            }
        }
    }
}

static constexpr int kSmem3_128 = 2 * (4 * kAMat);                    // 81920
static constexpr int kSmem3_64  = 2 * (2 * kAMat + 2 * 64 * kRowB);   // 61440
static constexpr int kSmem1_128 = 2 * (2 * kAMat);                    // 40960

// ================= fp32 SGEMM 64x128 tile (exact path for Q projection) ==========
__global__ void __launch_bounds__(256, 2)
sgemm_nt(const float* __restrict__ A, int lda,
         const float* __restrict__ B, int ldb,
         float* __restrict__ C, int ldc, int K)
{
    __shared__ float As[16][64];
    __shared__ float Bs[16][128];

    const int tid = threadIdx.x;
    const int m0  = blockIdx.y * 64;
    const int n0  = blockIdx.x * 128;

    const int lr = tid >> 2;
    const int lc = (tid & 3) << 2;
    const int tx = tid & 15;
    const int ty = tid >> 4;

    float acc[4][8];
#pragma unroll
    for (int i = 0; i < 4; i++)
#pragma unroll
        for (int j = 0; j < 8; j++) acc[i][j] = 0.f;

    for (int k0 = 0; k0 < K; k0 += 16) {
        float4 a0 = *(const float4*)(A + (long long)(m0 + lr)      * lda + k0 + lc);
        float4 b0 = *(const float4*)(B + (long long)(n0 + lr)      * ldb + k0 + lc);
        float4 b1 = *(const float4*)(B + (long long)(n0 + lr + 64) * ldb + k0 + lc);
        __syncthreads();
        As[lc + 0][lr] = a0.x; As[lc + 1][lr] = a0.y; As[lc + 2][lr] = a0.z; As[lc + 3][lr] = a0.w;
        Bs[lc + 0][lr] = b0.x; Bs[lc + 1][lr] = b0.y; Bs[lc + 2][lr] = b0.z; Bs[lc + 3][lr] = b0.w;
        Bs[lc + 0][lr + 64] = b1.x; Bs[lc + 1][lr + 64] = b1.y; Bs[lc + 2][lr + 64] = b1.z; Bs[lc + 3][lr + 64] = b1.w;
        __syncthreads();
#pragma unroll
        for (int kk = 0; kk < 16; kk++) {
            float4 av = *(const float4*)&As[kk][ty * 4];
            float4 bv0 = *(const float4*)&Bs[kk][tx * 8];
            float4 bv1 = *(const float4*)&Bs[kk][tx * 8 + 4];
            float a[4] = {av.x, av.y, av.z, av.w};
            float b[8] = {bv0.x, bv0.y, bv0.z, bv0.w, bv1.x, bv1.y, bv1.z, bv1.w};
#pragma unroll
            for (int i = 0; i < 4; i++)
#pragma unroll
                for (int j = 0; j < 8; j++) acc[i][j] = fmaf(a[i], b[j], acc[i][j]);
        }
    }

#pragma unroll
    for (int i = 0; i < 4; i++) {
        float* crow = C + (long long)(m0 + ty * 4 + i) * ldc + n0 + tx * 8;
#pragma unroll
        for (int j = 0; j < 8; j++) crow[j] = acc[i][j];
    }
}

// ================= splits =================
__global__ void split_kernel(const float* __restrict__ src,
                             __nv_bfloat16* __restrict__ hi,
                             __nv_bfloat16* __restrict__ lo, int n4)
{
    const int i = blockIdx.x * blockDim.x + threadIdx.x;
    if (i >= n4) return;
    const float4 v = ((const float4*)src)[i];
    __nv_bfloat16 h0 = __float2bfloat16(v.x);
    __nv_bfloat16 h1 = __float2bfloat16(v.y);
    __nv_bfloat16 h2 = __float2bfloat16(v.z);
    __nv_bfloat16 h3 = __float2bfloat16(v.w);
    __nv_bfloat162 H0; H0.x = h0; H0.y = h1;
    __nv_bfloat162 H1; H1.x = h2; H1.y = h3;
    __nv_bfloat162 L0, L1;
    L0.x = __float2bfloat16(v.x - __bfloat162float(h0));
    L0.y = __float2bfloat16(v.y - __bfloat162float(h1));
    L1.x = __float2bfloat16(v.z - __bfloat162float(h2));
    L1.y = __float2bfloat16(v.w - __bfloat162float(h3));
    ((__nv_bfloat162*)hi)[2 * i]     = H0;
    ((__nv_bfloat162*)hi)[2 * i + 1] = H1;
    ((__nv_bfloat162*)lo)[2 * i]     = L0;
    ((__nv_bfloat162*)lo)[2 * i + 1] = L1;
}

// sum of two fp32 buffers -> bf16 hi/lo split
__global__ void sumsplit_kernel(const float* __restrict__ a, const float* __restrict__ b,
                                __nv_bfloat16* __restrict__ hi,
                                __nv_bfloat16* __restrict__ lo, int n4)
{
    const int i = blockIdx.x * blockDim.x + threadIdx.x;
    if (i >= n4) return;
    const float4 va = ((const float4*)a)[i];
    const float4 vb = ((const float4*)b)[i];
    float4 v;
    v.x = va.x + vb.x; v.y = va.y + vb.y; v.z = va.z + vb.z; v.w = va.w + vb.w;
    __nv_bfloat16 h0 = __float2bfloat16(v.x);
    __nv_bfloat16 h1 = __float2bfloat16(v.y);
    __nv_bfloat16 h2 = __float2bfloat16(v.z);
    __nv_bfloat16 h3 = __float2bfloat16(v.w);
    __nv_bfloat162 H0; H0.x = h0; H0.y = h1;
    __nv_bfloat162 H1; H1.x = h2; H1.y = h3;
    __nv_bfloat162 L0, L1;
    L0.x = __float2bfloat16(v.x - __bfloat162float(h0));
    L0.y = __float2bfloat16(v.y - __bfloat162float(h1));
    L1.x = __float2bfloat16(v.z - __bfloat162float(h2));
    L1.y = __float2bfloat16(v.w - __bfloat162float(h3));
    ((__nv_bfloat162*)hi)[2 * i]     = H0;
    ((__nv_bfloat162*)hi)[2 * i + 1] = H1;
    ((__nv_bfloat162*)lo)[2 * i]     = L0;
    ((__nv_bfloat162*)lo)[2 * i + 1] = L1;
}

// strided split of g_qkv columns [0,4096) (local Q|K) -> g_lqk hi/lo [512 x 4096]
__global__ void qksplit_kernel()
{
    const int i = blockIdx.x * blockDim.x + threadIdx.x;   // over 512*1024 float4
    if (i >= kS * 1024) return;
    const int row = i >> 10;
    const int c4  = (i & 1023) << 2;
    const float4 v = *(const float4*)&g_qkv[(long long)row * kQKVld + c4];
    __nv_bfloat16 h0 = __float2bfloat16(v.x);
    __nv_bfloat16 h1 = __float2bfloat16(v.y);
    __nv_bfloat16 h2 = __float2bfloat16(v.z);
    __nv_bfloat16 h3 = __float2bfloat16(v.w);
    __nv_bfloat162 H0; H0.x = h0; H0.y = h1;
    __nv_bfloat162 H1; H1.x = h2; H1.y = h3;
    __nv_bfloat162 L0, L1;
    L0.x = __float2bfloat16(v.x - __bfloat162float(h0));
    L0.y = __float2bfloat16(v.y - __bfloat162float(h1));
    L1.x = __float2bfloat16(v.z - __bfloat162float(h2));
    L1.y = __float2bfloat16(v.w - __bfloat162float(h3));
    ((__nv_bfloat162*)g_lqk_h)[2 * i]     = H0;
    ((__nv_bfloat162*)g_lqk_h)[2 * i + 1] = H1;
    ((__nv_bfloat162*)g_lqk_l)[2 * i]     = L0;
    ((__nv_bfloat162*)g_lqk_l)[2 * i + 1] = L1;
}

// V local transpose + split: g_qkv V part [k][h*128+d] -> g_vT [h][d][k] bf16 hi/lo
__global__ void vtrans_kernel()
{
    __shared__ float t[32][33];
    const int h  = blockIdx.z;
    const int dt = blockIdx.y;
    const int kt = blockIdx.x;
    const int tx = threadIdx.x & 31;
    const int ty = threadIdx.x >> 5;   // 0..7
#pragma unroll
    for (int i = 0; i < 4; i++) {
        const int k = kt * 32 + ty + i * 8;
        t[ty + i * 8][tx] = g_qkv[(long long)k * kQKVld + 2 * kH + h * kD + dt * 32 + tx];
    }
    __syncthreads();
#pragma unroll
    for (int i = 0; i < 4; i++) {
        const int d = dt * 32 + ty + i * 8;
        const float val = t[tx][ty + i * 8];
        const long long o = ((long long)h * kD + d) * kS + kt * 32 + tx;
        const __nv_bfloat16 hi = __float2bfloat16(val);
        g_vT_h[o] = hi;
        g_vT_l[o] = __float2bfloat16(val - __bfloat162float(hi));
    }
}

__global__ void qsplit_kernel()
{
    const int gw   = (blockIdx.x * blockDim.x + threadIdx.x) >> 5;
    const int lane = threadIdx.x & 31;
    if (gw >= kNH * kS) return;
    const int h = gw >> 9;
    const int q = gw & 511;
    float4 v = *(const float4*)(g_qkv + (long long)q * kQKVld + h * kD + lane * 4);
    float s = v.x * v.x + v.y * v.y + v.z * v.z + v.w * v.w;
#pragma unroll
    for (int o = 16; o > 0; o >>= 1) s += __shfl_xor_sync(0xffffffffu, s, o);
    const float inv = rsqrtf(s);
    v.x *= inv; v.y *= inv; v.z *= inv; v.w *= inv;
    const long long base = (long long)gw * kD + lane * 4;
    *(float4*)(g_qn_f32 + base) = v;
    __nv_bfloat162 H0, H1;
    H0.x = __float2bfloat16(v.x); H0.y = __float2bfloat16(v.y);
    H1.x = __float2bfloat16(v.z); H1.y = __float2bfloat16(v.w);
    *(__nv_bfloat162*)(g_qn_h + base)     = H0;
    *(__nv_bfloat162*)(g_qn_h + base + 2) = H1;
}

__global__ void ksplit_kernel(const float* __restrict__ kc)
{
    const int gw   = (blockIdx.x * blockDim.x + threadIdx.x) >> 5;
    const int lane = threadIdx.x & 31;
    if (gw >= kNH * kSC) return;
    float4 v = *(const float4*)(kc + (long long)gw * kD + lane * 4);
    float s = v.x * v.x + v.y * v.y + v.z * v.z + v.w * v.w;
#pragma unroll
    for (int o = 16; o > 0; o >>= 1) s += __shfl_xor_sync(0xffffffffu, s, o);
    const float inv = rsqrtf(s);
    v.x *= inv; v.y *= inv; v.z *= inv; v.w *= inv;
    const long long base = (long long)gw * kD + lane * 4;
    *(float4*)(g_kn_f32 + base) = v;
    __nv_bfloat162 H0, H1;
    H0.x = __float2bfloat16(v.x); H0.y = __float2bfloat16(v.y);
    H1.x = __float2bfloat16(v.z); H1.y = __float2bfloat16(v.w);
    *(__nv_bfloat162*)(g_kn_h + base)     = H0;
    *(__nv_bfloat162*)(g_kn_h + base + 2) = H1;
}

// ---------------- per-(h,q) approx top-32 over 8192 packed keys ----------------
// R13 block tournament (proven): packed = key16 << 13 | (8191 - idx).
__global__ void __launch_bounds__(256)
topk_kernel()
{
    const long long row = blockIdx.x;  // h*512 + q
    const uint16_t* sim = g_simkey + row * kSC;
    const int tid = threadIdx.x;
    const int lane = tid & 31;
    const int w = tid >> 5;

    uint32_t v[32];
#pragma unroll
    for (int c = 0; c < 4; c++) {
        const int base = c * 2048 + tid * 8;
        uint4 raw = *(const uint4*)(sim + base);
        const uint32_t words[4] = {raw.x, raw.y, raw.z, raw.w};
#pragma unroll
        for (int j = 0; j < 4; j++) {
            const uint32_t lo = words[j] & 0xFFFFu;
            const uint32_t hi = words[j] >> 16;
            v[c * 8 + 2 * j]     = (lo << 13) | (uint32_t)(8191 - (base + 2 * j));
            v[c * 8 + 2 * j + 1] = (hi << 13) | (uint32_t)(8191 - (base + 2 * j + 1));
        }
    }

    uint32_t locmax = 0;
#pragma unroll
    for (int i = 0; i < 32; i++) locmax = max(locmax, v[i]);

    __shared__ uint32_t wv[8];
    __shared__ uint32_t bshare;

    for (int r = 0; r < kCand; r++) {
        const uint32_t wm = __reduce_max_sync(0xffffffffu, locmax);
        if (lane == 0) wv[w] = wm;
        __syncthreads();
        if (tid == 0) {
            uint32_t b = wv[0];
#pragma unroll
            for (int k = 1; k < 8; k++) b = max(b, wv[k]);
            bshare = b;
            g_cand[row * kCand + r] = 8191 - (int)(b & 8191u);
        }
        __syncthreads();
        const uint32_t best = bshare;
        if (locmax == best) {
            uint32_t nm = 0;
#pragma unroll
            for (int i = 0; i < 32; i++) {
                if (v[i] == best) v[i] = 0;
                nm = max(nm, v[i]);
            }
            locmax = nm;
        }
    }
}

// ---------------- exact rescore of 32 candidates -> exact top-16 ----------------
__global__ void __launch_bounds__(256)
rescore_kernel()
{
    const int gw   = (blockIdx.x * blockDim.x + threadIdx.x) >> 5;
    const int lane = threadIdx.x & 31;
    if (gw >= kNH * kS) return;
    const int h = gw >> 9;

    const float4 qv = *(const float4*)(g_qn_f32 + (long long)gw * kD + lane * 4);
    int   myidx = g_cand[gw * kCand + lane];
    float myval = -FLT_MAX;

    for (int c = 0; c < kCand; c++) {
        const int idx = __shfl_sync(0xffffffffu, myidx, c);
        const float4 kv = *(const float4*)(g_kn_f32 + ((long long)h * kSC + idx) * kD + lane * 4);
        float p = qv.x * kv.x + qv.y * kv.y + qv.z * kv.z + qv.w * kv.w;
#pragma unroll
        for (int o = 16; o > 0; o >>= 1) p += __shfl_xor_sync(0xffffffffu, p, o);
        if (lane == c) myval = p;
    }

    for (int r = 0; r < kTopK; r++) {
        float v = myval; int ix = myidx;
#pragma unroll
        for (int o = 16; o > 0; o >>= 1) {
            float ov = __shfl_xor_sync(0xffffffffu, v, o);
            int   oi = __shfl_xor_sync(0xffffffffu, ix, o);
            if (ov > v || (ov == v && oi < ix)) { v = ov; ix = oi; }
        }
        if (lane == 0) {
            g_topv[gw * kTopK + r] = v;
            g_topi[gw * kTopK + r] = ix;
        }
        if (myidx == ix) myval = -FLT_MAX;
    }
}

// ---------------- softmax + ext context per (h,q) ----------------
__global__ void __launch_bounds__(256)
softmax_kernel(const float* __restrict__ kc, const float* __restrict__ vc,
               const float* __restrict__ bias)
{
    const int q = blockIdx.x;
    const int h = blockIdx.y;
    const int tid = threadIdx.x;
    const int lane = tid & 31;
    const int w = tid >> 5;

    __shared__ float qs[128];
    __shared__ float ssc[16 + kS];
    __shared__ int   sidx[16];
    __shared__ float redw[8];
    __shared__ float bmax, bsuminv;

    const long long rowhq = (long long)h * kS + q;

    if (tid < 128) qs[tid] = g_qkv[(long long)q * kQKVld + h * kD + tid];
    if (tid < 16)  sidx[tid] = g_topi[rowhq * 16 + tid];
    __syncthreads();

    const float4 qv = *(const float4*)(qs + lane * 4);

    for (int j = w; j < 16; j += 8) {
        float s;
        if (g_topv[rowhq * 16 + j] > kSimTh) {
            const float* kp = kc + ((long long)h * kSC + sidx[j]) * kD;
            float4 kv = *(const float4*)(kp + lane * 4);
            float p = qv.x * kv.x + qv.y * kv.y + qv.z * kv.z + qv.w * kv.w;
#pragma unroll
            for (int o = 16; o > 0; o >>= 1) p += __shfl_down_sync(0xffffffffu, p, o);
            s = p * kScale;
        } else {
            s = kNeg;
        }
        if (lane == 0) ssc[j] = s;
    }

    const float* srow  = g_scores + rowhq * kS;
    const float* brow  = bias + rowhq * kS;
    for (int j = tid; j < kS; j += 256) {
        ssc[16 + j] = (j <= q) ? srow[j] * kScale + brow[j] : kNeg;
    }
    __syncthreads();

    float m = -FLT_MAX;
    for (int j = tid; j < 16 + kS; j += 256) m = fmaxf(m, ssc[j]);
#pragma unroll
    for (int o = 16; o > 0; o >>= 1) m = fmaxf(m, __shfl_down_sync(0xffffffffu, m, o));
    if (lane == 0) redw[w] = m;
    __syncthreads();
    if (tid == 0) {
        float mm = redw[0];
#pragma unroll
        for (int k = 1; k < 8; k++) mm = fmaxf(mm, redw[k]);
        bmax = mm;
    }
    __syncthreads();
    const float msc = bmax;
    float ss = 0.f;
    for (int j = tid; j < 16 + kS; j += 256) {
        float e = __expf(ssc[j] - msc);
        ssc[j] = e;
        ss += e;
    }
#pragma unroll
    for (int o = 16; o > 0; o >>= 1) ss += __shfl_down_sync(0xffffffffu, ss, o);
    if (lane == 0) redw[w] = ss;
    __syncthreads();
    if (tid == 0) {
        float t = 0.f;
#pragma unroll
        for (int k = 0; k < 8; k++) t += redw[k];
        bsuminv = 1.f / t;
    }
    __syncthreads();
    const float inv = bsuminv;

    for (int j = tid; j < kS; j += 256) {
        const float p = ssc[16 + j] * inv;
        const __nv_bfloat16 hi = __float2bfloat16(p);
        g_pl_h[rowhq * kS + j] = hi;
        g_pl_l[rowhq * kS + j] = __float2bfloat16(p - __bfloat162float(hi));
    }

    if (tid < 128) {
        float acc = 0.f;
        for (int j = 0; j < 16; j++) {
            const float p = ssc[j] * inv;
            if (p > 0.f) acc += p * vc[((long long)h * kSC + sidx[j]) * kD + tid];
        }
        g_ctxe[(long long)q * kH + h * kD + tid] = acc;
    }
}

// ---------------- launcher ----------------
extern "C" void kernel_launch(void* const* d_in, const int* in_sizes, int n_in,
                              void* d_out, int out_size)
{
    const float* hidden = (const float*)d_in[0];
    const float* Wqkv   = (const float*)d_in[1];
    const float* Wout   = (const float*)d_in[2];
    const float* kc     = (const float*)d_in[3];
    const float* vc     = (const float*)d_in[4];
    const float* bias   = (const float*)d_in[5];
    float* out = (float*)d_out;

    float *p_qkv, *p_scores, *p_ctxe, *p_ctxl;
    uint16_t* p_simkey;
    cudaGetSymbolAddress((void**)&p_qkv,    g_qkv);
    cudaGetSymbolAddress((void**)&p_simkey, g_simkey);
    cudaGetSymbolAddress((void**)&p_scores, g_scores);
    cudaGetSymbolAddress((void**)&p_ctxe,   g_ctxe);
    cudaGetSymbolAddress((void**)&p_ctxl,   g_ctxl);
    __nv_bfloat16 *p_hid_h, *p_hid_l, *p_wqkv_h, *p_wqkv_l, *p_wout_h, *p_wout_l;
    __nv_bfloat16 *p_qn_h, *p_kn_h, *p_ctx_h, *p_ctx_l;
    __nv_bfloat16 *p_lqk_h, *p_lqk_l, *p_vT_h, *p_vT_l, *p_pl_h, *p_pl_l;
    cudaGetSymbolAddress((void**)&p_hid_h,  g_hid_h);
    cudaGetSymbolAddress((void**)&p_hid_l,  g_hid_l);
    cudaGetSymbolAddress((void**)&p_wqkv_h, g_wqkv_h);
    cudaGetSymbolAddress((void**)&p_wqkv_l, g_wqkv_l);
    cudaGetSymbolAddress((void**)&p_wout_h, g_wout_h);
    cudaGetSymbolAddress((void**)&p_wout_l, g_wout_l);
    cudaGetSymbolAddress((void**)&p_qn_h,   g_qn_h);
    cudaGetSymbolAddress((void**)&p_kn_h,   g_kn_h);
    cudaGetSymbolAddress((void**)&p_ctx_h,  g_ctx_h);
    cudaGetSymbolAddress((void**)&p_ctx_l,  g_ctx_l);
    cudaGetSymbolAddress((void**)&p_lqk_h,  g_lqk_h);
    cudaGetSymbolAddress((void**)&p_lqk_l,  g_lqk_l);
    cudaGetSymbolAddress((void**)&p_vT_h,   g_vT_h);
    cudaGetSymbolAddress((void**)&p_vT_l,   g_vT_l);
    cudaGetSymbolAddress((void**)&p_pl_h,   g_pl_h);
    cudaGetSymbolAddress((void**)&p_pl_l,   g_pl_l);

    cudaFuncSetAttribute((const void*)mma_gemm<3, false, 128, 1>, cudaFuncAttributeMaxDynamicSharedMemorySize, kSmem3_128);
    cudaFuncSetAttribute((const void*)mma_gemm<3, false, 64, 0>,  cudaFuncAttributeMaxDynamicSharedMemorySize, kSmem3_64);
    cudaFuncSetAttribute((const void*)mma_gemm<3, false, 64, 2>,  cudaFuncAttributeMaxDynamicSharedMemorySize, kSmem3_64);
    cudaFuncSetAttribute((const void*)mma_gemm<1, true, 128, 0>,  cudaFuncAttributeMaxDynamicSharedMemorySize, kSmem1_128);

    // ---- selection chain first (sim mma = launch #3 for ncu visibility) ----
    ksplit_kernel<<<(kNH * kSC * 32) / 256, 256>>>(kc);
    sgemm_nt<<<dim3(kH / 128, kS / 64), 256>>>(hidden, kH, Wqkv, kH, p_qkv, kQKVld, kH);
    qsplit_kernel<<<(kNH * kS * 32) / 256, 256>>>();
    mma_gemm<1, true, 128, 0><<<dim3(kSC / 128, kS / 128, kNH), 256, kSmem1_128>>>(
        p_qn_h, nullptr, p_kn_h, nullptr, p_simkey,
        kD, kD, kSC,
        (long long)kS * kD, (long long)kSC * kD, (long long)kS * kSC, kD);
    topk_kernel<<<kNH * kS, 256>>>();
    rescore_kernel<<<(kNH * kS * 32 + 255) / 256, 256>>>();

    // ---- projection / attention chain ----
    split_kernel<<<(4096 * kH / 4 + 255) / 256, 256>>>(Wqkv + (size_t)2048 * kH, p_wqkv_h, p_wqkv_l, 4096 * kH / 4);
    split_kernel<<<(kS * kH / 4 + 255) / 256, 256>>>(hidden, p_hid_h, p_hid_l, kS * kH / 4);
    mma_gemm<3, false, 64, 0><<<dim3(4096 / 64, kS / 128, 1), 256, kSmem3_64>>>(
        p_hid_h, p_hid_l, p_wqkv_h, p_wqkv_l,
        p_qkv + 2048, kH, kH, kQKVld, 0, 0, 0, kH);

    // local QK^T (causal: skip fully-masked upper tiles — outputs never read)
    qksplit_kernel<<<(kS * 1024 + 255) / 256, 256>>>();
    mma_gemm<3, false, 128, 1><<<dim3(kS / 128, kS / 128, kNH), 256, kSmem3_128>>>(
        p_lqk_h, p_lqk_l, p_lqk_h + 2048, p_lqk_l + 2048,
        p_scores, 4096, 4096, kS,
        128, 128, (long long)kS * kS, kD);

    vtrans_kernel<<<dim3(kS / 32, kD / 32, kNH), 256>>>();

    softmax_kernel<<<dim3(kS, kNH), 256>>>(kc, vc, bias);

    // local PV (causal: clamp K to m0+128 — skipped P columns are exactly zero)
    mma_gemm<3, false, 64, 2><<<dim3(kD / 64, kS / 128, kNH), 256, kSmem3_64>>>(
        p_pl_h, p_pl_l, p_vT_h, p_vT_l,
        p_ctxl, kS, kS, kH,
        (long long)kS * kS, (long long)kD * kS, 128, kS);

    split_kernel<<<(kH * kH / 4 + 255) / 256, 256>>>(Wout, p_wout_h, p_wout_l, kH * kH / 4);
    sumsplit_kernel<<<(kS * kH / 4 + 255) / 256, 256>>>(p_ctxl, p_ctxe, p_ctx_h, p_ctx_l, kS * kH / 4);
    mma_gemm<3, false, 64, 0><<<dim3(kH / 64, kS / 128, 1), 256, kSmem3_64>>>(
        p_ctx_h, p_ctx_l, p_wout_h, p_wout_l, out,
        kH, kH, kH, 0, 0, 0, kH);
}